// round 1
// baseline (speedup 1.0000x reference)
#include <cuda_runtime.h>
#include <cuda_bf16.h>
#include <math.h>

#define D_MODEL 2048
#define T_SEQ   2048
#define BATCH   2
#define N_HEADS 32
#define N_KV    8
#define D_KH    64
#define KV_DIM  (N_KV * D_KH)      // 512
#define M_ROWS  (BATCH * T_SEQ)    // 4096

// ---------------------------------------------------------------------------
// Scratch (allocation-free rule: __device__ globals)
// ---------------------------------------------------------------------------
__device__ float g_Q [M_ROWS * D_MODEL];   // 32 MB
__device__ float g_K [M_ROWS * KV_DIM];    //  8 MB
__device__ float g_V [M_ROWS * KV_DIM];    //  8 MB
__device__ float g_AO[M_ROWS * D_MODEL];   // 32 MB (attention output, pre-Wo)

// ---------------------------------------------------------------------------
// GEMM: Y[M,N] = X[M,K] @ W[N,K]^T   (torch Linear layout, both K-contiguous)
// BM=BN=128, BK=16, 256 threads, 8x8 microtile.
// ---------------------------------------------------------------------------
__global__ __launch_bounds__(256) void gemm_xwt(
    const float* __restrict__ X, const float* __restrict__ W,
    float* __restrict__ Y, int M, int N, int K)
{
    __shared__ float Xs[16][128];
    __shared__ float Ws[16][128];

    const int bn = blockIdx.x * 128;
    const int bm = blockIdx.y * 128;
    const int t  = threadIdx.x;
    const int tx = t & 15;      // 16 col-threads
    const int ty = t >> 4;      // 16 row-threads

    float acc[8][8];
#pragma unroll
    for (int i = 0; i < 8; i++)
#pragma unroll
        for (int j = 0; j < 8; j++) acc[i][j] = 0.f;

    for (int k0 = 0; k0 < K; k0 += 16) {
        // Stage tiles transposed: Xs[k][m], Ws[k][n]. 2048 floats each = 512 float4.
#pragma unroll
        for (int i = 0; i < 2; i++) {
            int idx = t + i * 256;         // float4 index
            int row = idx >> 2;            // 0..127
            int c4  = (idx & 3) * 4;       // 0,4,8,12
            float4 xv = *(const float4*)(X + (size_t)(bm + row) * K + k0 + c4);
            Xs[c4 + 0][row] = xv.x; Xs[c4 + 1][row] = xv.y;
            Xs[c4 + 2][row] = xv.z; Xs[c4 + 3][row] = xv.w;
            float4 wv = *(const float4*)(W + (size_t)(bn + row) * K + k0 + c4);
            Ws[c4 + 0][row] = wv.x; Ws[c4 + 1][row] = wv.y;
            Ws[c4 + 2][row] = wv.z; Ws[c4 + 3][row] = wv.w;
        }
        __syncthreads();

#pragma unroll
        for (int k = 0; k < 16; k++) {
            float4 a0 = *(const float4*)&Xs[k][ty * 8];
            float4 a1 = *(const float4*)&Xs[k][ty * 8 + 4];
            float4 b0 = *(const float4*)&Ws[k][tx * 4];         // cols tx*4..+3
            float4 b1 = *(const float4*)&Ws[k][64 + tx * 4];    // cols 64+tx*4..+3
            float a[8] = {a0.x, a0.y, a0.z, a0.w, a1.x, a1.y, a1.z, a1.w};
            float b[8] = {b0.x, b0.y, b0.z, b0.w, b1.x, b1.y, b1.z, b1.w};
#pragma unroll
            for (int i = 0; i < 8; i++)
#pragma unroll
                for (int j = 0; j < 8; j++) acc[i][j] += a[i] * b[j];
        }
        __syncthreads();
    }

#pragma unroll
    for (int i = 0; i < 8; i++) {
        size_t r = (size_t)(bm + ty * 8 + i);
        float4 o0 = make_float4(acc[i][0], acc[i][1], acc[i][2], acc[i][3]);
        float4 o1 = make_float4(acc[i][4], acc[i][5], acc[i][6], acc[i][7]);
        *(float4*)(Y + r * N + bn + tx * 4)      = o0;
        *(float4*)(Y + r * N + bn + 64 + tx * 4) = o1;
    }
}

// ---------------------------------------------------------------------------
// Fused causal GQA attention (flash-style, fp32).
// Grid: (T/64 q-tiles, N_HEADS, BATCH). Block: 256 threads.
// Each block: 64 q-rows x d=64, streams 64-row K/V tiles with online softmax.
// ---------------------------------------------------------------------------
#define BQ 64
#define PAD 65

__global__ __launch_bounds__(256) void attn_kernel(
    const float* __restrict__ Q, const float* __restrict__ K,
    const float* __restrict__ V, float* __restrict__ O)
{
    extern __shared__ float sm[];
    float* Qs   = sm;                   // [64][65]
    float* Ks   = Qs + BQ * PAD;        // [64][65]
    float* Vs   = Ks + BQ * PAD;        // [64][65]
    float* Ps   = Vs + BQ * PAD;        // [64][65]  (scores / probs)
    float* mrow = Ps + BQ * PAD;        // [64]
    float* lrow = mrow + BQ;            // [64]
    float* arow = lrow + BQ;            // [64]

    const int qt = blockIdx.x;
    const int h  = blockIdx.y;
    const int b  = blockIdx.z;
    const int kv = h >> 2;              // N_REP = 4

    const int t  = threadIdx.x;
    const int tx = t & 15;
    const int ty = t >> 4;
    const float scale = 0.125f;         // 1/sqrt(64)

    // Load Q tile: rows qt*64..+63, cols h*64..+63 of [4096, 2048]
    const float* Qb = Q + ((size_t)(b * T_SEQ + qt * BQ)) * D_MODEL + h * D_KH;
#pragma unroll
    for (int i = 0; i < 4; i++) {
        int idx = t + i * 256;          // float4 index, 1024 total
        int row = idx >> 4;             // 16 float4 per row
        int c   = (idx & 15) * 4;
        float4 v = *(const float4*)(Qb + (size_t)row * D_MODEL + c);
        Qs[row * PAD + c + 0] = v.x; Qs[row * PAD + c + 1] = v.y;
        Qs[row * PAD + c + 2] = v.z; Qs[row * PAD + c + 3] = v.w;
    }
    if (t < BQ) { mrow[t] = -1e30f; lrow[t] = 0.f; }

    float acc[4][4];
#pragma unroll
    for (int i = 0; i < 4; i++)
#pragma unroll
        for (int j = 0; j < 4; j++) acc[i][j] = 0.f;

    __syncthreads();

    for (int kt = 0; kt <= qt; kt++) {
        const float* Kb = K + ((size_t)(b * T_SEQ + kt * BQ)) * KV_DIM + kv * D_KH;
        const float* Vb = V + ((size_t)(b * T_SEQ + kt * BQ)) * KV_DIM + kv * D_KH;
#pragma unroll
        for (int i = 0; i < 4; i++) {
            int idx = t + i * 256;
            int row = idx >> 4;
            int c   = (idx & 15) * 4;
            float4 kvv = *(const float4*)(Kb + (size_t)row * KV_DIM + c);
            Ks[row * PAD + c + 0] = kvv.x; Ks[row * PAD + c + 1] = kvv.y;
            Ks[row * PAD + c + 2] = kvv.z; Ks[row * PAD + c + 3] = kvv.w;
            float4 vv = *(const float4*)(Vb + (size_t)row * KV_DIM + c);
            Vs[row * PAD + c + 0] = vv.x; Vs[row * PAD + c + 1] = vv.y;
            Vs[row * PAD + c + 2] = vv.z; Vs[row * PAD + c + 3] = vv.w;
        }
        __syncthreads();

        // S = Qs @ Ks^T  (each thread: 4x4 of 64x64)
        float s[4][4];
#pragma unroll
        for (int i = 0; i < 4; i++)
#pragma unroll
            for (int j = 0; j < 4; j++) s[i][j] = 0.f;
#pragma unroll 8
        for (int d = 0; d < 64; d++) {
            float a[4], bb[4];
#pragma unroll
            for (int i = 0; i < 4; i++) a[i]  = Qs[(ty * 4 + i) * PAD + d];
#pragma unroll
            for (int j = 0; j < 4; j++) bb[j] = Ks[(tx * 4 + j) * PAD + d];
#pragma unroll
            for (int i = 0; i < 4; i++)
#pragma unroll
                for (int j = 0; j < 4; j++) s[i][j] += a[i] * bb[j];
        }

        const bool diag = (kt == qt);
#pragma unroll
        for (int i = 0; i < 4; i++) {
            int r = ty * 4 + i;
#pragma unroll
            for (int j = 0; j < 4; j++) {
                int c = tx * 4 + j;
                float v = s[i][j] * scale;
                if (diag && c > r) v = -1e30f;
                Ps[r * PAD + c] = v;
            }
        }
        __syncthreads();

        // Online softmax per row (64 row-threads)
        if (t < BQ) {
            float m0 = mrow[t];
            float mx = m0;
#pragma unroll 8
            for (int j = 0; j < BQ; j++) mx = fmaxf(mx, Ps[t * PAD + j]);
            float sum = 0.f;
#pragma unroll 8
            for (int j = 0; j < BQ; j++) {
                float p = __expf(Ps[t * PAD + j] - mx);
                Ps[t * PAD + j] = p;
                sum += p;
            }
            float al = __expf(m0 - mx);
            mrow[t] = mx;
            lrow[t] = lrow[t] * al + sum;
            arow[t] = al;
        }
        __syncthreads();

        // O = O*alpha + P @ Vs
#pragma unroll
        for (int i = 0; i < 4; i++) {
            float al = arow[ty * 4 + i];
#pragma unroll
            for (int j = 0; j < 4; j++) acc[i][j] *= al;
        }
#pragma unroll 8
        for (int jk = 0; jk < BQ; jk++) {
            float p[4], vv[4];
#pragma unroll
            for (int i = 0; i < 4; i++) p[i]  = Ps[(ty * 4 + i) * PAD + jk];
#pragma unroll
            for (int j = 0; j < 4; j++) vv[j] = Vs[jk * PAD + tx * 4 + j];
#pragma unroll
            for (int i = 0; i < 4; i++)
#pragma unroll
                for (int j = 0; j < 4; j++) acc[i][j] += p[i] * vv[j];
        }
        __syncthreads();
    }

    // Epilogue: divide by l, write back
    float* Ob = O + ((size_t)(b * T_SEQ + qt * BQ)) * D_MODEL + h * D_KH;
#pragma unroll
    for (int i = 0; i < 4; i++) {
        int r = ty * 4 + i;
        float inv_l = 1.0f / lrow[r];
        float4 o = make_float4(acc[i][0] * inv_l, acc[i][1] * inv_l,
                               acc[i][2] * inv_l, acc[i][3] * inv_l);
        *(float4*)(Ob + (size_t)r * D_MODEL + tx * 4) = o;
    }
}

// ---------------------------------------------------------------------------
// Launch
// ---------------------------------------------------------------------------
static const int ATTN_SMEM = (4 * BQ * PAD + 3 * BQ) * (int)sizeof(float); // 67328

extern "C" void kernel_launch(void* const* d_in, const int* in_sizes, int n_in,
                              void* d_out, int out_size)
{
    const float* x  = (const float*)d_in[0];
    const float* Wq = (const float*)d_in[1];
    const float* Wk = (const float*)d_in[2];
    const float* Wv = (const float*)d_in[3];
    const float* Wo = (const float*)d_in[4];
    float* out = (float*)d_out;

    float *Q, *K, *V, *AO;
    cudaGetSymbolAddress((void**)&Q,  g_Q);
    cudaGetSymbolAddress((void**)&K,  g_K);
    cudaGetSymbolAddress((void**)&V,  g_V);
    cudaGetSymbolAddress((void**)&AO, g_AO);

    cudaFuncSetAttribute(attn_kernel,
                         cudaFuncAttributeMaxDynamicSharedMemorySize, ATTN_SMEM);

    // Projections
    gemm_xwt<<<dim3(D_MODEL / 128, M_ROWS / 128), 256>>>(x, Wq, Q, M_ROWS, D_MODEL, D_MODEL);
    gemm_xwt<<<dim3(KV_DIM  / 128, M_ROWS / 128), 256>>>(x, Wk, K, M_ROWS, KV_DIM,  D_MODEL);
    gemm_xwt<<<dim3(KV_DIM  / 128, M_ROWS / 128), 256>>>(x, Wv, V, M_ROWS, KV_DIM,  D_MODEL);

    // Fused causal GQA attention
    attn_kernel<<<dim3(T_SEQ / BQ, N_HEADS, BATCH), 256, ATTN_SMEM>>>(Q, K, V, AO);

    // Output projection
    gemm_xwt<<<dim3(D_MODEL / 128, M_ROWS / 128), 256>>>(AO, Wo, out, M_ROWS, D_MODEL, D_MODEL);
}

// round 4
// speedup vs baseline: 1.6080x; 1.6080x over previous
#include <cuda_runtime.h>
#include <cuda_bf16.h>
#include <math.h>
#include <cstdint>

#define D_MODEL 2048
#define T_SEQ   2048
#define BATCH   2
#define N_HEADS 32
#define N_KV    8
#define D_KH    64
#define KV_DIM  (N_KV * D_KH)      // 512
#define M_ROWS  (BATCH * T_SEQ)    // 4096
#define GK      2048

// ---------------------------------------------------------------------------
// Scratch (__device__ globals; allocation-free rule)
// ---------------------------------------------------------------------------
__device__ float g_Q [M_ROWS * D_MODEL];
__device__ float g_K [M_ROWS * KV_DIM];
__device__ float g_V [M_ROWS * KV_DIM];
__device__ float g_AO[M_ROWS * D_MODEL];

__device__ __nv_bfloat16 g_xhi [M_ROWS * D_MODEL];
__device__ __nv_bfloat16 g_xlo [M_ROWS * D_MODEL];
__device__ __nv_bfloat16 g_aohi[M_ROWS * D_MODEL];
__device__ __nv_bfloat16 g_aolo[M_ROWS * D_MODEL];
__device__ __nv_bfloat16 g_wqhi[D_MODEL * D_MODEL];
__device__ __nv_bfloat16 g_wqlo[D_MODEL * D_MODEL];
__device__ __nv_bfloat16 g_wkhi[KV_DIM * D_MODEL];
__device__ __nv_bfloat16 g_wklo[KV_DIM * D_MODEL];
__device__ __nv_bfloat16 g_wvhi[KV_DIM * D_MODEL];
__device__ __nv_bfloat16 g_wvlo[KV_DIM * D_MODEL];
__device__ __nv_bfloat16 g_wohi[D_MODEL * D_MODEL];
__device__ __nv_bfloat16 g_wolo[D_MODEL * D_MODEL];

// ---------------------------------------------------------------------------
// Helpers
// ---------------------------------------------------------------------------
__device__ __forceinline__ uint32_t smem_u32(const void* p) {
    uint32_t a;
    asm("{ .reg .u64 t; cvta.to.shared.u64 t, %1; cvt.u32.u64 %0, t; }" : "=r"(a) : "l"(p));
    return a;
}
#define CP_ASYNC16(dst, src) \
    asm volatile("cp.async.cg.shared.global [%0], [%1], 16;" :: "r"(dst), "l"(src) : "memory")
#define CP_COMMIT() asm volatile("cp.async.commit_group;" ::: "memory")
#define CP_WAIT1()  asm volatile("cp.async.wait_group 1;" ::: "memory")

__device__ __forceinline__ void ldsm_x4(uint32_t& r0, uint32_t& r1, uint32_t& r2, uint32_t& r3, uint32_t a) {
    asm volatile("ldmatrix.sync.aligned.m8n8.x4.shared.b16 {%0,%1,%2,%3}, [%4];"
                 : "=r"(r0), "=r"(r1), "=r"(r2), "=r"(r3) : "r"(a));
}
__device__ __forceinline__ void ldsm_x2(uint32_t& r0, uint32_t& r1, uint32_t a) {
    asm volatile("ldmatrix.sync.aligned.m8n8.x2.shared.b16 {%0,%1}, [%2];"
                 : "=r"(r0), "=r"(r1) : "r"(a));
}
__device__ __forceinline__ void mma_bf16(float* c, const uint32_t* a, const uint32_t* b) {
    asm volatile("mma.sync.aligned.m16n8k16.row.col.f32.bf16.bf16.f32 "
                 "{%0,%1,%2,%3}, {%4,%5,%6,%7}, {%8,%9}, {%0,%1,%2,%3};"
                 : "+f"(c[0]), "+f"(c[1]), "+f"(c[2]), "+f"(c[3])
                 : "r"(a[0]), "r"(a[1]), "r"(a[2]), "r"(a[3]), "r"(b[0]), "r"(b[1]));
}

// ---------------------------------------------------------------------------
// fp32 -> (bf16 hi, bf16 lo) split
// ---------------------------------------------------------------------------
__global__ __launch_bounds__(256) void split_bf16(
    const float* __restrict__ s, __nv_bfloat16* __restrict__ hi,
    __nv_bfloat16* __restrict__ lo, int n)
{
    int i = (blockIdx.x * 256 + threadIdx.x) * 4;
    if (i >= n) return;
    float4 v = *(const float4*)(s + i);
    __nv_bfloat16 h0 = __float2bfloat16(v.x), h1 = __float2bfloat16(v.y);
    __nv_bfloat16 h2 = __float2bfloat16(v.z), h3 = __float2bfloat16(v.w);
    __nv_bfloat16 l0 = __float2bfloat16(v.x - __bfloat162float(h0));
    __nv_bfloat16 l1 = __float2bfloat16(v.y - __bfloat162float(h1));
    __nv_bfloat16 l2 = __float2bfloat16(v.z - __bfloat162float(h2));
    __nv_bfloat16 l3 = __float2bfloat16(v.w - __bfloat162float(h3));
    *(__nv_bfloat162*)(hi + i)     = __nv_bfloat162(h0, h1);
    *(__nv_bfloat162*)(hi + i + 2) = __nv_bfloat162(h2, h3);
    *(__nv_bfloat162*)(lo + i)     = __nv_bfloat162(l0, l1);
    *(__nv_bfloat162*)(lo + i + 2) = __nv_bfloat162(l2, l3);
}

// ---------------------------------------------------------------------------
// HMMA GEMM: Y[M,N] = A[M,2048] @ B[N,2048]^T  (fp32 via 3-term bf16 split)
// CTA 128x128, BK=32, 8 warps (warp tile 64x32), cp.async double buffer.
// Smem row stride 80B (32 bf16 + 8 pad).
// ---------------------------------------------------------------------------
#define RS      80                    // bytes per smem row
#define TILE_B  (128 * RS)            // 10240 per tile
#define STG_B   (4 * TILE_B)          // 40960 per stage
#define GEMM_SMEM (2 * STG_B)         // 81920

__global__ __launch_bounds__(256) void gemm_hmma(
    const __nv_bfloat16* __restrict__ Ahi, const __nv_bfloat16* __restrict__ Alo,
    const __nv_bfloat16* __restrict__ Bhi, const __nv_bfloat16* __restrict__ Blo,
    float* __restrict__ Y, int N)
{
    extern __shared__ __align__(128) char smem[];
    const uint32_t sb = smem_u32(smem);

    const int t   = threadIdx.x;
    const int wid = t >> 5, l = t & 31;
    const int wm  = wid & 1, wn = wid >> 1;    // 2 x 4 warp grid
    const int bm  = blockIdx.y * 128, bn = blockIdx.x * 128;

    const __nv_bfloat16* srcs[4] = {Ahi + (size_t)bm * GK, Alo + (size_t)bm * GK,
                                    Bhi + (size_t)bn * GK, Blo + (size_t)bn * GK};

    // Per-thread cp.async slots: 8 chunks of 16B (2048 chunks total)
    int c_tile[8], c_dst[8];
    size_t c_src[8];
#pragma unroll
    for (int c = 0; c < 8; c++) {
        int chunk = t + c * 256;
        int tile = chunk >> 9;            // /512
        int idx  = chunk & 511;
        int row  = idx >> 2;
        int k16  = idx & 3;
        c_tile[c] = tile;
        c_dst[c]  = tile * TILE_B + row * RS + k16 * 16;
        c_src[c]  = (size_t)row * GK + k16 * 8;
    }

    auto load_stage = [&](int s, int k0) {
        uint32_t base = sb + s * STG_B;
#pragma unroll
        for (int c = 0; c < 8; c++)
            CP_ASYNC16(base + c_dst[c], (const char*)(srcs[c_tile[c]] + k0 + c_src[c]));
    };

    float acc[4][4][4];
#pragma unroll
    for (int i = 0; i < 4; i++)
#pragma unroll
        for (int j = 0; j < 4; j++)
#pragma unroll
            for (int k = 0; k < 4; k++) acc[i][j][k] = 0.f;

    // Lane base addresses for ldmatrix
    const uint32_t aBase = sb + (uint32_t)((wm * 64 + (l & 15)) * RS + (l >> 4) * 16);
    const uint32_t bBase = sb + 2 * TILE_B + (uint32_t)((wn * 32 + (l & 7)) * RS + ((l & 15) >> 3) * 16);

    const int nIter = GK / 32;    // 64
    load_stage(0, 0);
    CP_COMMIT();

    for (int it = 0; it < nIter; it++) {
        if (it + 1 < nIter) load_stage((it + 1) & 1, (it + 1) * 32);
        CP_COMMIT();
        CP_WAIT1();
        __syncthreads();

        const uint32_t so = (uint32_t)((it & 1) * STG_B);
#pragma unroll
        for (int ks = 0; ks < 2; ks++) {
            const uint32_t kb = so + ks * 32;
            uint32_t ah[4][4], al[4][4], bh[4][2], bl[4][2];
#pragma unroll
            for (int mt = 0; mt < 4; mt++) {
                uint32_t a = aBase + kb + mt * 16 * RS;
                ldsm_x4(ah[mt][0], ah[mt][1], ah[mt][2], ah[mt][3], a);
                ldsm_x4(al[mt][0], al[mt][1], al[mt][2], al[mt][3], a + TILE_B);
            }
#pragma unroll
            for (int nt = 0; nt < 4; nt++) {
                uint32_t a = bBase + kb + nt * 8 * RS;
                ldsm_x2(bh[nt][0], bh[nt][1], a);
                ldsm_x2(bl[nt][0], bl[nt][1], a + TILE_B);
            }
#pragma unroll
            for (int mt = 0; mt < 4; mt++)
#pragma unroll
                for (int nt = 0; nt < 4; nt++) {
                    mma_bf16(acc[mt][nt], ah[mt], bh[nt]);
                    mma_bf16(acc[mt][nt], ah[mt], bl[nt]);
                    mma_bf16(acc[mt][nt], al[mt], bh[nt]);
                }
        }
        __syncthreads();
    }

    // Epilogue
    const int r0c = bm + wm * 64 + (l >> 2);
    const int col0 = bn + wn * 32 + (l & 3) * 2;
#pragma unroll
    for (int mt = 0; mt < 4; mt++) {
#pragma unroll
        for (int nt = 0; nt < 4; nt++) {
            float* y0 = Y + (size_t)(r0c + mt * 16) * N + col0 + nt * 8;
            float* y1 = y0 + 8 * N;
            y0[0] = acc[mt][nt][0]; y0[1] = acc[mt][nt][1];
            y1[0] = acc[mt][nt][2]; y1[1] = acc[mt][nt][3];
        }
    }
}

// ---------------------------------------------------------------------------
// Fused causal GQA attention (flash-style, fp32) — unchanged
// ---------------------------------------------------------------------------
#define BQ 64
#define PAD 65

__global__ __launch_bounds__(256) void attn_kernel(
    const float* __restrict__ Q, const float* __restrict__ K,
    const float* __restrict__ V, float* __restrict__ O)
{
    extern __shared__ float sm[];
    float* Qs   = sm;
    float* Ks   = Qs + BQ * PAD;
    float* Vs   = Ks + BQ * PAD;
    float* Ps   = Vs + BQ * PAD;
    float* mrow = Ps + BQ * PAD;
    float* lrow = mrow + BQ;
    float* arow = lrow + BQ;

    const int qt = blockIdx.x;
    const int h  = blockIdx.y;
    const int b  = blockIdx.z;
    const int kv = h >> 2;

    const int t  = threadIdx.x;
    const int tx = t & 15;
    const int ty = t >> 4;
    const float scale = 0.125f;

    const float* Qb = Q + ((size_t)(b * T_SEQ + qt * BQ)) * D_MODEL + h * D_KH;
#pragma unroll
    for (int i = 0; i < 4; i++) {
        int idx = t + i * 256;
        int row = idx >> 4;
        int c   = (idx & 15) * 4;
        float4 v = *(const float4*)(Qb + (size_t)row * D_MODEL + c);
        Qs[row * PAD + c + 0] = v.x; Qs[row * PAD + c + 1] = v.y;
        Qs[row * PAD + c + 2] = v.z; Qs[row * PAD + c + 3] = v.w;
    }
    if (t < BQ) { mrow[t] = -1e30f; lrow[t] = 0.f; }

    float acc[4][4];
#pragma unroll
    for (int i = 0; i < 4; i++)
#pragma unroll
        for (int j = 0; j < 4; j++) acc[i][j] = 0.f;

    __syncthreads();

    for (int kt = 0; kt <= qt; kt++) {
        const float* Kb = K + ((size_t)(b * T_SEQ + kt * BQ)) * KV_DIM + kv * D_KH;
        const float* Vb = V + ((size_t)(b * T_SEQ + kt * BQ)) * KV_DIM + kv * D_KH;
#pragma unroll
        for (int i = 0; i < 4; i++) {
            int idx = t + i * 256;
            int row = idx >> 4;
            int c   = (idx & 15) * 4;
            float4 kvv = *(const float4*)(Kb + (size_t)row * KV_DIM + c);
            Ks[row * PAD + c + 0] = kvv.x; Ks[row * PAD + c + 1] = kvv.y;
            Ks[row * PAD + c + 2] = kvv.z; Ks[row * PAD + c + 3] = kvv.w;
            float4 vv = *(const float4*)(Vb + (size_t)row * KV_DIM + c);
            Vs[row * PAD + c + 0] = vv.x; Vs[row * PAD + c + 1] = vv.y;
            Vs[row * PAD + c + 2] = vv.z; Vs[row * PAD + c + 3] = vv.w;
        }
        __syncthreads();

        float s[4][4];
#pragma unroll
        for (int i = 0; i < 4; i++)
#pragma unroll
            for (int j = 0; j < 4; j++) s[i][j] = 0.f;
#pragma unroll 8
        for (int d = 0; d < 64; d++) {
            float a[4], bb[4];
#pragma unroll
            for (int i = 0; i < 4; i++) a[i]  = Qs[(ty * 4 + i) * PAD + d];
#pragma unroll
            for (int j = 0; j < 4; j++) bb[j] = Ks[(tx * 4 + j) * PAD + d];
#pragma unroll
            for (int i = 0; i < 4; i++)
#pragma unroll
                for (int j = 0; j < 4; j++) s[i][j] += a[i] * bb[j];
        }

        const bool diag = (kt == qt);
#pragma unroll
        for (int i = 0; i < 4; i++) {
            int r = ty * 4 + i;
#pragma unroll
            for (int j = 0; j < 4; j++) {
                int c = tx * 4 + j;
                float v = s[i][j] * scale;
                if (diag && c > r) v = -1e30f;
                Ps[r * PAD + c] = v;
            }
        }
        __syncthreads();

        if (t < BQ) {
            float m0 = mrow[t];
            float mx = m0;
#pragma unroll 8
            for (int j = 0; j < BQ; j++) mx = fmaxf(mx, Ps[t * PAD + j]);
            float sum = 0.f;
#pragma unroll 8
            for (int j = 0; j < BQ; j++) {
                float p = __expf(Ps[t * PAD + j] - mx);
                Ps[t * PAD + j] = p;
                sum += p;
            }
            float al = __expf(m0 - mx);
            mrow[t] = mx;
            lrow[t] = lrow[t] * al + sum;
            arow[t] = al;
        }
        __syncthreads();

#pragma unroll
        for (int i = 0; i < 4; i++) {
            float al = arow[ty * 4 + i];
#pragma unroll
            for (int j = 0; j < 4; j++) acc[i][j] *= al;
        }
#pragma unroll 8
        for (int jk = 0; jk < BQ; jk++) {
            float p[4], vv[4];
#pragma unroll
            for (int i = 0; i < 4; i++) p[i]  = Ps[(ty * 4 + i) * PAD + jk];
#pragma unroll
            for (int j = 0; j < 4; j++) vv[j] = Vs[jk * PAD + tx * 4 + j];
#pragma unroll
            for (int i = 0; i < 4; i++)
#pragma unroll
                for (int j = 0; j < 4; j++) acc[i][j] += p[i] * vv[j];
        }
        __syncthreads();
    }

    float* Ob = O + ((size_t)(b * T_SEQ + qt * BQ)) * D_MODEL + h * D_KH;
#pragma unroll
    for (int i = 0; i < 4; i++) {
        int r = ty * 4 + i;
        float inv_l = 1.0f / lrow[r];
        float4 o = make_float4(acc[i][0] * inv_l, acc[i][1] * inv_l,
                               acc[i][2] * inv_l, acc[i][3] * inv_l);
        *(float4*)(Ob + (size_t)r * D_MODEL + tx * 4) = o;
    }
}

// ---------------------------------------------------------------------------
// Launch
// ---------------------------------------------------------------------------
static const int ATTN_SMEM = (4 * BQ * PAD + 3 * BQ) * (int)sizeof(float);

extern "C" void kernel_launch(void* const* d_in, const int* in_sizes, int n_in,
                              void* d_out, int out_size)
{
    const float* x  = (const float*)d_in[0];
    const float* Wq = (const float*)d_in[1];
    const float* Wk = (const float*)d_in[2];
    const float* Wv = (const float*)d_in[3];
    const float* Wo = (const float*)d_in[4];
    float* out = (float*)d_out;

    float *Q, *K, *V, *AO;
    cudaGetSymbolAddress((void**)&Q,  g_Q);
    cudaGetSymbolAddress((void**)&K,  g_K);
    cudaGetSymbolAddress((void**)&V,  g_V);
    cudaGetSymbolAddress((void**)&AO, g_AO);

    __nv_bfloat16 *xhi, *xlo, *aohi, *aolo, *wqhi, *wqlo, *wkhi, *wklo, *wvhi, *wvlo, *wohi, *wolo;
    cudaGetSymbolAddress((void**)&xhi,  g_xhi);  cudaGetSymbolAddress((void**)&xlo,  g_xlo);
    cudaGetSymbolAddress((void**)&aohi, g_aohi); cudaGetSymbolAddress((void**)&aolo, g_aolo);
    cudaGetSymbolAddress((void**)&wqhi, g_wqhi); cudaGetSymbolAddress((void**)&wqlo, g_wqlo);
    cudaGetSymbolAddress((void**)&wkhi, g_wkhi); cudaGetSymbolAddress((void**)&wklo, g_wklo);
    cudaGetSymbolAddress((void**)&wvhi, g_wvhi); cudaGetSymbolAddress((void**)&wvlo, g_wvlo);
    cudaGetSymbolAddress((void**)&wohi, g_wohi); cudaGetSymbolAddress((void**)&wolo, g_wolo);

    cudaFuncSetAttribute(attn_kernel, cudaFuncAttributeMaxDynamicSharedMemorySize, ATTN_SMEM);
    cudaFuncSetAttribute(gemm_hmma,   cudaFuncAttributeMaxDynamicSharedMemorySize, GEMM_SMEM);

    const int NX  = M_ROWS * D_MODEL;
    const int NWQ = D_MODEL * D_MODEL;
    const int NWK = KV_DIM * D_MODEL;

    split_bf16<<<NX  / 1024, 256>>>(x,  xhi,  xlo,  NX);
    split_bf16<<<NWQ / 1024, 256>>>(Wq, wqhi, wqlo, NWQ);
    split_bf16<<<NWK / 1024, 256>>>(Wk, wkhi, wklo, NWK);
    split_bf16<<<NWK / 1024, 256>>>(Wv, wvhi, wvlo, NWK);
    split_bf16<<<NWQ / 1024, 256>>>(Wo, wohi, wolo, NWQ);

    gemm_hmma<<<dim3(D_MODEL / 128, M_ROWS / 128), 256, GEMM_SMEM>>>(xhi, xlo, wqhi, wqlo, Q, D_MODEL);
    gemm_hmma<<<dim3(KV_DIM  / 128, M_ROWS / 128), 256, GEMM_SMEM>>>(xhi, xlo, wkhi, wklo, K, KV_DIM);
    gemm_hmma<<<dim3(KV_DIM  / 128, M_ROWS / 128), 256, GEMM_SMEM>>>(xhi, xlo, wvhi, wvlo, V, KV_DIM);

    attn_kernel<<<dim3(T_SEQ / BQ, N_HEADS, BATCH), 256, ATTN_SMEM>>>(Q, K, V, AO);

    split_bf16<<<NX / 1024, 256>>>(AO, aohi, aolo, NX);
    gemm_hmma<<<dim3(D_MODEL / 128, M_ROWS / 128), 256, GEMM_SMEM>>>(aohi, aolo, wohi, wolo, out, D_MODEL);
}

// round 6
// speedup vs baseline: 2.7449x; 1.7070x over previous
#include <cuda_runtime.h>
#include <cuda_bf16.h>
#include <math.h>
#include <cstdint>

#define D_MODEL 2048
#define T_SEQ   2048
#define BATCH   2
#define N_HEADS 32
#define N_KV    8
#define D_KH    64
#define KV_DIM  (N_KV * D_KH)      // 512
#define M_ROWS  (BATCH * T_SEQ)    // 4096
#define GK      2048

// ---------------------------------------------------------------------------
// Scratch (__device__ globals; allocation-free rule)
// ---------------------------------------------------------------------------
__device__ float g_Q [M_ROWS * D_MODEL];
__device__ float g_K [M_ROWS * KV_DIM];
__device__ float g_V [M_ROWS * KV_DIM];
__device__ float g_AO[M_ROWS * D_MODEL];

__device__ __nv_bfloat16 g_xhi [M_ROWS * D_MODEL];
__device__ __nv_bfloat16 g_xlo [M_ROWS * D_MODEL];
__device__ __nv_bfloat16 g_aohi[M_ROWS * D_MODEL];
__device__ __nv_bfloat16 g_aolo[M_ROWS * D_MODEL];
__device__ __nv_bfloat16 g_wqhi[D_MODEL * D_MODEL];
__device__ __nv_bfloat16 g_wqlo[D_MODEL * D_MODEL];
__device__ __nv_bfloat16 g_wkhi[KV_DIM * D_MODEL];
__device__ __nv_bfloat16 g_wklo[KV_DIM * D_MODEL];
__device__ __nv_bfloat16 g_wvhi[KV_DIM * D_MODEL];
__device__ __nv_bfloat16 g_wvlo[KV_DIM * D_MODEL];
__device__ __nv_bfloat16 g_wohi[D_MODEL * D_MODEL];
__device__ __nv_bfloat16 g_wolo[D_MODEL * D_MODEL];

// ---------------------------------------------------------------------------
// Helpers
// ---------------------------------------------------------------------------
__device__ __forceinline__ uint32_t smem_u32(const void* p) {
    uint32_t a;
    asm("{ .reg .u64 t; cvta.to.shared.u64 t, %1; cvt.u32.u64 %0, t; }" : "=r"(a) : "l"(p));
    return a;
}
#define CP_ASYNC16(dst, src) \
    asm volatile("cp.async.cg.shared.global [%0], [%1], 16;" :: "r"(dst), "l"(src) : "memory")
#define CP_COMMIT() asm volatile("cp.async.commit_group;" ::: "memory")
#define CP_WAIT1()  asm volatile("cp.async.wait_group 1;" ::: "memory")

__device__ __forceinline__ void ldsm_x4(uint32_t& r0, uint32_t& r1, uint32_t& r2, uint32_t& r3, uint32_t a) {
    asm volatile("ldmatrix.sync.aligned.m8n8.x4.shared.b16 {%0,%1,%2,%3}, [%4];"
                 : "=r"(r0), "=r"(r1), "=r"(r2), "=r"(r3) : "r"(a));
}
__device__ __forceinline__ void ldsm_x4_t(uint32_t& r0, uint32_t& r1, uint32_t& r2, uint32_t& r3, uint32_t a) {
    asm volatile("ldmatrix.sync.aligned.m8n8.x4.trans.shared.b16 {%0,%1,%2,%3}, [%4];"
                 : "=r"(r0), "=r"(r1), "=r"(r2), "=r"(r3) : "r"(a));
}
__device__ __forceinline__ void ldsm_x2(uint32_t& r0, uint32_t& r1, uint32_t a) {
    asm volatile("ldmatrix.sync.aligned.m8n8.x2.shared.b16 {%0,%1}, [%2];"
                 : "=r"(r0), "=r"(r1) : "r"(a));
}
__device__ __forceinline__ void mma_bf16(float* c, const uint32_t* a, const uint32_t* b) {
    asm volatile("mma.sync.aligned.m16n8k16.row.col.f32.bf16.bf16.f32 "
                 "{%0,%1,%2,%3}, {%4,%5,%6,%7}, {%8,%9}, {%0,%1,%2,%3};"
                 : "+f"(c[0]), "+f"(c[1]), "+f"(c[2]), "+f"(c[3])
                 : "r"(a[0]), "r"(a[1]), "r"(a[2]), "r"(a[3]), "r"(b[0]), "r"(b[1]));
}
__device__ __forceinline__ uint32_t pack_bf16(float lo, float hi) {
    uint32_t r;
    asm("cvt.rn.bf16x2.f32 %0, %1, %2;" : "=r"(r) : "f"(hi), "f"(lo));
    return r;
}
__device__ __forceinline__ float bf16_round(float v) {
    return __bfloat162float(__float2bfloat16(v));
}

// ---------------------------------------------------------------------------
// fp32 -> (bf16 hi, bf16 lo) split
// ---------------------------------------------------------------------------
__global__ __launch_bounds__(256) void split_bf16(
    const float* __restrict__ s, __nv_bfloat16* __restrict__ hi,
    __nv_bfloat16* __restrict__ lo, int n)
{
    int i = (blockIdx.x * 256 + threadIdx.x) * 4;
    if (i >= n) return;
    float4 v = *(const float4*)(s + i);
    __nv_bfloat16 h0 = __float2bfloat16(v.x), h1 = __float2bfloat16(v.y);
    __nv_bfloat16 h2 = __float2bfloat16(v.z), h3 = __float2bfloat16(v.w);
    __nv_bfloat16 l0 = __float2bfloat16(v.x - __bfloat162float(h0));
    __nv_bfloat16 l1 = __float2bfloat16(v.y - __bfloat162float(h1));
    __nv_bfloat16 l2 = __float2bfloat16(v.z - __bfloat162float(h2));
    __nv_bfloat16 l3 = __float2bfloat16(v.w - __bfloat162float(h3));
    *(__nv_bfloat162*)(hi + i)     = __nv_bfloat162(h0, h1);
    *(__nv_bfloat162*)(hi + i + 2) = __nv_bfloat162(h2, h3);
    *(__nv_bfloat162*)(lo + i)     = __nv_bfloat162(l0, l1);
    *(__nv_bfloat162*)(lo + i + 2) = __nv_bfloat162(l2, l3);
}

// ---------------------------------------------------------------------------
// HMMA GEMM (unchanged from passing R4)
// ---------------------------------------------------------------------------
#define RS      80
#define TILE_B  (128 * RS)
#define STG_B   (4 * TILE_B)
#define GEMM_SMEM (2 * STG_B)

__global__ __launch_bounds__(256) void gemm_hmma(
    const __nv_bfloat16* __restrict__ Ahi, const __nv_bfloat16* __restrict__ Alo,
    const __nv_bfloat16* __restrict__ Bhi, const __nv_bfloat16* __restrict__ Blo,
    float* __restrict__ Y, int N)
{
    extern __shared__ __align__(128) char smem[];
    const uint32_t sb = smem_u32(smem);

    const int t   = threadIdx.x;
    const int wid = t >> 5, l = t & 31;
    const int wm  = wid & 1, wn = wid >> 1;
    const int bm  = blockIdx.y * 128, bn = blockIdx.x * 128;

    const __nv_bfloat16* srcs[4] = {Ahi + (size_t)bm * GK, Alo + (size_t)bm * GK,
                                    Bhi + (size_t)bn * GK, Blo + (size_t)bn * GK};

    int c_tile[8], c_dst[8];
    size_t c_src[8];
#pragma unroll
    for (int c = 0; c < 8; c++) {
        int chunk = t + c * 256;
        int tile = chunk >> 9;
        int idx  = chunk & 511;
        int row  = idx >> 2;
        int k16  = idx & 3;
        c_tile[c] = tile;
        c_dst[c]  = tile * TILE_B + row * RS + k16 * 16;
        c_src[c]  = (size_t)row * GK + k16 * 8;
    }

    auto load_stage = [&](int s, int k0) {
        uint32_t base = sb + s * STG_B;
#pragma unroll
        for (int c = 0; c < 8; c++)
            CP_ASYNC16(base + c_dst[c], (const char*)(srcs[c_tile[c]] + k0 + c_src[c]));
    };

    float acc[4][4][4];
#pragma unroll
    for (int i = 0; i < 4; i++)
#pragma unroll
        for (int j = 0; j < 4; j++)
#pragma unroll
            for (int k = 0; k < 4; k++) acc[i][j][k] = 0.f;

    const uint32_t aBase = sb + (uint32_t)((wm * 64 + (l & 15)) * RS + (l >> 4) * 16);
    const uint32_t bBase = sb + 2 * TILE_B + (uint32_t)((wn * 32 + (l & 7)) * RS + ((l & 15) >> 3) * 16);

    const int nIter = GK / 32;
    load_stage(0, 0);
    CP_COMMIT();

    for (int it = 0; it < nIter; it++) {
        if (it + 1 < nIter) load_stage((it + 1) & 1, (it + 1) * 32);
        CP_COMMIT();
        CP_WAIT1();
        __syncthreads();

        const uint32_t so = (uint32_t)((it & 1) * STG_B);
#pragma unroll
        for (int ks = 0; ks < 2; ks++) {
            const uint32_t kb = so + ks * 32;
            uint32_t ah[4][4], al[4][4], bh[4][2], bl[4][2];
#pragma unroll
            for (int mt = 0; mt < 4; mt++) {
                uint32_t a = aBase + kb + mt * 16 * RS;
                ldsm_x4(ah[mt][0], ah[mt][1], ah[mt][2], ah[mt][3], a);
                ldsm_x4(al[mt][0], al[mt][1], al[mt][2], al[mt][3], a + TILE_B);
            }
#pragma unroll
            for (int nt = 0; nt < 4; nt++) {
                uint32_t a = bBase + kb + nt * 8 * RS;
                ldsm_x2(bh[nt][0], bh[nt][1], a);
                ldsm_x2(bl[nt][0], bl[nt][1], a + TILE_B);
            }
#pragma unroll
            for (int mt = 0; mt < 4; mt++)
#pragma unroll
                for (int nt = 0; nt < 4; nt++) {
                    mma_bf16(acc[mt][nt], ah[mt], bh[nt]);
                    mma_bf16(acc[mt][nt], ah[mt], bl[nt]);
                    mma_bf16(acc[mt][nt], al[mt], bh[nt]);
                }
        }
        __syncthreads();
    }

    const int r0c = bm + wm * 64 + (l >> 2);
    const int col0 = bn + wn * 32 + (l & 3) * 2;
#pragma unroll
    for (int mt = 0; mt < 4; mt++) {
#pragma unroll
        for (int nt = 0; nt < 4; nt++) {
            float* y0 = Y + (size_t)(r0c + mt * 16) * N + col0 + nt * 8;
            float* y1 = y0 + 8 * N;
            y0[0] = acc[mt][nt][0]; y0[1] = acc[mt][nt][1];
            y1[0] = acc[mt][nt][2]; y1[1] = acc[mt][nt][3];
        }
    }
}

// ---------------------------------------------------------------------------
// HMMA flash attention, causal GQA, fp32-accurate via hi/lo bf16 splits.
// CTA: 64 q-rows x one (b,h). 128 threads = 4 warps, 16 q-rows/warp.
// ---------------------------------------------------------------------------
#define ATS  72                         // bf16 elems per smem row
#define ATSB (64 * ATS * 2)             // 9216 bytes per tile
#define ATTN_SMEM (6 * ATSB)            // 55296

__global__ __launch_bounds__(128) void attn_hmma(
    const float* __restrict__ Q, const float* __restrict__ K,
    const float* __restrict__ V, float* __restrict__ O)
{
    extern __shared__ __align__(128) char smem[];
    const uint32_t sb  = smem_u32(smem);
    const uint32_t qhi = sb,            qlo = sb + ATSB;
    const uint32_t khi = sb + 2 * ATSB, klo = sb + 3 * ATSB;
    const uint32_t vhi = sb + 4 * ATSB, vlo = sb + 5 * ATSB;

    const int qt = blockIdx.x;
    const int h  = blockIdx.y;
    const int b  = blockIdx.z;
    const int kv = h >> 2;

    const int t = threadIdx.x;
    const int w = t >> 5, l = t & 31;
    const float scale = 0.125f;

    // ---- Stage Q tile (fp32 -> hi/lo bf16, padded rows) ----
    const float* Qg = Q + ((size_t)(b * T_SEQ + qt * 64)) * D_MODEL + h * D_KH;
#pragma unroll
    for (int i = 0; i < 8; i++) {
        int idx = i * 128 + t;           // float4 index, 1024 total
        int row = idx >> 4;
        int c4  = (idx & 15) * 4;
        float4 v = *(const float4*)(Qg + (size_t)row * D_MODEL + c4);
        float h0 = bf16_round(v.x), h1 = bf16_round(v.y), h2 = bf16_round(v.z), h3 = bf16_round(v.w);
        uint32_t off = (uint32_t)(row * (ATS * 2) + c4 * 2);
        *(uint2*)(smem + (qhi - sb) + off) = make_uint2(pack_bf16(h0, h1), pack_bf16(h2, h3));
        *(uint2*)(smem + (qlo - sb) + off) = make_uint2(pack_bf16(v.x - h0, v.y - h1),
                                                        pack_bf16(v.z - h2, v.w - h3));
    }
    __syncthreads();

    // ---- Q fragments (loop-invariant) ----
    uint32_t aqh[4][4], aql[4][4];
#pragma unroll
    for (int kc = 0; kc < 4; kc++) {
        uint32_t a = qhi + (uint32_t)((w * 16 + (l & 15)) * (ATS * 2) + kc * 32 + (l >> 4) * 16);
        ldsm_x4(aqh[kc][0], aqh[kc][1], aqh[kc][2], aqh[kc][3], a);
        ldsm_x4(aql[kc][0], aql[kc][1], aql[kc][2], aql[kc][3], a + ATSB);
    }

    float o[8][4];
#pragma unroll
    for (int i = 0; i < 8; i++)
#pragma unroll
        for (int j = 0; j < 4; j++) o[i][j] = 0.f;
    float m0 = -1e30f, m1 = -1e30f, l0 = 0.f, l1 = 0.f;

    for (int kt = 0; kt <= qt; kt++) {
        __syncthreads();   // previous iter's smem reads done
        // ---- Stage K,V tiles (fp32 -> hi/lo) ----
        const float* Kg = K + ((size_t)(b * T_SEQ + kt * 64)) * KV_DIM + kv * D_KH;
        const float* Vg = V + ((size_t)(b * T_SEQ + kt * 64)) * KV_DIM + kv * D_KH;
#pragma unroll
        for (int i = 0; i < 8; i++) {
            int idx = i * 128 + t;
            int row = idx >> 4;
            int c4  = (idx & 15) * 4;
            uint32_t off = (uint32_t)(row * (ATS * 2) + c4 * 2);
            float4 kx = *(const float4*)(Kg + (size_t)row * KV_DIM + c4);
            float k0 = bf16_round(kx.x), k1 = bf16_round(kx.y), k2 = bf16_round(kx.z), k3 = bf16_round(kx.w);
            *(uint2*)(smem + (khi - sb) + off) = make_uint2(pack_bf16(k0, k1), pack_bf16(k2, k3));
            *(uint2*)(smem + (klo - sb) + off) = make_uint2(pack_bf16(kx.x - k0, kx.y - k1),
                                                            pack_bf16(kx.z - k2, kx.w - k3));
            float4 vx = *(const float4*)(Vg + (size_t)row * KV_DIM + c4);
            float v0 = bf16_round(vx.x), v1 = bf16_round(vx.y), v2 = bf16_round(vx.z), v3 = bf16_round(vx.w);
            *(uint2*)(smem + (vhi - sb) + off) = make_uint2(pack_bf16(v0, v1), pack_bf16(v2, v3));
            *(uint2*)(smem + (vlo - sb) + off) = make_uint2(pack_bf16(vx.x - v0, vx.y - v1),
                                                            pack_bf16(vx.z - v2, vx.w - v3));
        }
        __syncthreads();

        // ---- S = Q @ K^T (3-term split) ----
        float s[8][4];
#pragma unroll
        for (int i = 0; i < 8; i++)
#pragma unroll
            for (int j = 0; j < 4; j++) s[i][j] = 0.f;

#pragma unroll
        for (int nt = 0; nt < 8; nt++) {
#pragma unroll
            for (int kcp = 0; kcp < 2; kcp++) {
                uint32_t a = khi + (uint32_t)((nt * 8 + (l & 7)) * (ATS * 2) + kcp * 64 + (l >> 3) * 16);
                uint32_t h0, h1, h2, h3, g0, g1, g2, g3;
                ldsm_x4(h0, h1, h2, h3, a);
                ldsm_x4(g0, g1, g2, g3, a + ATSB);
                uint32_t bh0[2] = {h0, h1}, bh1[2] = {h2, h3};
                uint32_t bl0[2] = {g0, g1}, bl1[2] = {g2, g3};
                mma_bf16(s[nt], aqh[2 * kcp],     bh0);
                mma_bf16(s[nt], aqh[2 * kcp],     bl0);
                mma_bf16(s[nt], aql[2 * kcp],     bh0);
                mma_bf16(s[nt], aqh[2 * kcp + 1], bh1);
                mma_bf16(s[nt], aqh[2 * kcp + 1], bl1);
                mma_bf16(s[nt], aql[2 * kcp + 1], bh1);
            }
        }

        // ---- scale + causal mask ----
        const int rl0 = w * 16 + (l >> 2);      // local row (group 0)
        const bool diag = (kt == qt);
#pragma unroll
        for (int nt = 0; nt < 8; nt++) {
            int c0 = nt * 8 + (l & 3) * 2;
#pragma unroll
            for (int j = 0; j < 4; j++) {
                float v = s[nt][j] * scale;
                int c = c0 + (j & 1);
                int r = rl0 + ((j >> 1) << 3);
                if (diag && c > r) v = -1e30f;
                s[nt][j] = v;
            }
        }

        // ---- register online softmax (rows rl0, rl0+8) ----
        float mx0 = -1e30f, mx1 = -1e30f;
#pragma unroll
        for (int nt = 0; nt < 8; nt++) {
            mx0 = fmaxf(mx0, fmaxf(s[nt][0], s[nt][1]));
            mx1 = fmaxf(mx1, fmaxf(s[nt][2], s[nt][3]));
        }
        mx0 = fmaxf(mx0, __shfl_xor_sync(0xffffffff, mx0, 1));
        mx0 = fmaxf(mx0, __shfl_xor_sync(0xffffffff, mx0, 2));
        mx1 = fmaxf(mx1, __shfl_xor_sync(0xffffffff, mx1, 1));
        mx1 = fmaxf(mx1, __shfl_xor_sync(0xffffffff, mx1, 2));

        float mn0 = fmaxf(m0, mx0), mn1 = fmaxf(m1, mx1);
        float al0 = __expf(m0 - mn0), al1 = __expf(m1 - mn1);
        m0 = mn0; m1 = mn1;

        float sum0 = 0.f, sum1 = 0.f;
#pragma unroll
        for (int nt = 0; nt < 8; nt++) {
            s[nt][0] = __expf(s[nt][0] - mn0); sum0 += s[nt][0];
            s[nt][1] = __expf(s[nt][1] - mn0); sum0 += s[nt][1];
            s[nt][2] = __expf(s[nt][2] - mn1); sum1 += s[nt][2];
            s[nt][3] = __expf(s[nt][3] - mn1); sum1 += s[nt][3];
        }
        sum0 += __shfl_xor_sync(0xffffffff, sum0, 1);
        sum0 += __shfl_xor_sync(0xffffffff, sum0, 2);
        sum1 += __shfl_xor_sync(0xffffffff, sum1, 1);
        sum1 += __shfl_xor_sync(0xffffffff, sum1, 2);
        l0 = l0 * al0 + sum0;
        l1 = l1 * al1 + sum1;

#pragma unroll
        for (int nt = 0; nt < 8; nt++) {
            o[nt][0] *= al0; o[nt][1] *= al0;
            o[nt][2] *= al1; o[nt][3] *= al1;
        }

        // ---- O += P @ V (3-term split; P packed in registers) ----
#pragma unroll
        for (int kc2 = 0; kc2 < 4; kc2++) {
            float p00 = s[2 * kc2][0],     p01 = s[2 * kc2][1];
            float p02 = s[2 * kc2][2],     p03 = s[2 * kc2][3];
            float p10 = s[2 * kc2 + 1][0], p11 = s[2 * kc2 + 1][1];
            float p12 = s[2 * kc2 + 1][2], p13 = s[2 * kc2 + 1][3];
            float q00 = bf16_round(p00), q01 = bf16_round(p01), q02 = bf16_round(p02), q03 = bf16_round(p03);
            float q10 = bf16_round(p10), q11 = bf16_round(p11), q12 = bf16_round(p12), q13 = bf16_round(p13);
            uint32_t aph[4] = {pack_bf16(q00, q01), pack_bf16(q02, q03),
                               pack_bf16(q10, q11), pack_bf16(q12, q13)};
            uint32_t apl[4] = {pack_bf16(p00 - q00, p01 - q01), pack_bf16(p02 - q02, p03 - q03),
                               pack_bf16(p10 - q10, p11 - q11), pack_bf16(p12 - q12, p13 - q13)};
#pragma unroll
            for (int ntp = 0; ntp < 4; ntp++) {
                uint32_t a = vhi + (uint32_t)((kc2 * 16 + (l & 15)) * (ATS * 2) + ntp * 32 + (l >> 4) * 16);
                uint32_t h0, h1, h2, h3, g0, g1, g2, g3;
                ldsm_x4_t(h0, h1, h2, h3, a);
                ldsm_x4_t(g0, g1, g2, g3, a + ATSB);
                uint32_t bh0[2] = {h0, h1}, bh1[2] = {h2, h3};
                uint32_t bl0[2] = {g0, g1}, bl1[2] = {g2, g3};
                mma_bf16(o[2 * ntp],     aph, bh0);
                mma_bf16(o[2 * ntp],     aph, bl0);
                mma_bf16(o[2 * ntp],     apl, bh0);
                mma_bf16(o[2 * ntp + 1], aph, bh1);
                mma_bf16(o[2 * ntp + 1], aph, bl1);
                mma_bf16(o[2 * ntp + 1], apl, bh1);
            }
        }
    }

    // ---- epilogue ----
    const float il0 = 1.0f / l0, il1 = 1.0f / l1;
    const size_t row0 = (size_t)(b * T_SEQ + qt * 64 + w * 16 + (l >> 2));
    float* Ob = O + row0 * D_MODEL + h * D_KH + (l & 3) * 2;
#pragma unroll
    for (int nt = 0; nt < 8; nt++) {
        *(float2*)(Ob + nt * 8)                = make_float2(o[nt][0] * il0, o[nt][1] * il0);
        *(float2*)(Ob + nt * 8 + 8 * D_MODEL)  = make_float2(o[nt][2] * il1, o[nt][3] * il1);
    }
}

// ---------------------------------------------------------------------------
// Launch
// ---------------------------------------------------------------------------
extern "C" void kernel_launch(void* const* d_in, const int* in_sizes, int n_in,
                              void* d_out, int out_size)
{
    const float* x  = (const float*)d_in[0];
    const float* Wq = (const float*)d_in[1];
    const float* Wk = (const float*)d_in[2];
    const float* Wv = (const float*)d_in[3];
    const float* Wo = (const float*)d_in[4];
    float* out = (float*)d_out;

    float *Q, *K, *V, *AO;
    cudaGetSymbolAddress((void**)&Q,  g_Q);
    cudaGetSymbolAddress((void**)&K,  g_K);
    cudaGetSymbolAddress((void**)&V,  g_V);
    cudaGetSymbolAddress((void**)&AO, g_AO);

    __nv_bfloat16 *xhi, *xlo, *aohi, *aolo, *wqhi, *wqlo, *wkhi, *wklo, *wvhi, *wvlo, *wohi, *wolo;
    cudaGetSymbolAddress((void**)&xhi,  g_xhi);  cudaGetSymbolAddress((void**)&xlo,  g_xlo);
    cudaGetSymbolAddress((void**)&aohi, g_aohi); cudaGetSymbolAddress((void**)&aolo, g_aolo);
    cudaGetSymbolAddress((void**)&wqhi, g_wqhi); cudaGetSymbolAddress((void**)&wqlo, g_wqlo);
    cudaGetSymbolAddress((void**)&wkhi, g_wkhi); cudaGetSymbolAddress((void**)&wklo, g_wklo);
    cudaGetSymbolAddress((void**)&wvhi, g_wvhi); cudaGetSymbolAddress((void**)&wvlo, g_wvlo);
    cudaGetSymbolAddress((void**)&wohi, g_wohi); cudaGetSymbolAddress((void**)&wolo, g_wolo);

    cudaFuncSetAttribute(gemm_hmma, cudaFuncAttributeMaxDynamicSharedMemorySize, GEMM_SMEM);
    cudaFuncSetAttribute(attn_hmma, cudaFuncAttributeMaxDynamicSharedMemorySize, ATTN_SMEM);

    const int NX  = M_ROWS * D_MODEL;
    const int NWQ = D_MODEL * D_MODEL;
    const int NWK = KV_DIM * D_MODEL;

    split_bf16<<<NX  / 1024, 256>>>(x,  xhi,  xlo,  NX);
    split_bf16<<<NWQ / 1024, 256>>>(Wq, wqhi, wqlo, NWQ);
    split_bf16<<<NWK / 1024, 256>>>(Wk, wkhi, wklo, NWK);
    split_bf16<<<NWK / 1024, 256>>>(Wv, wvhi, wvlo, NWK);
    split_bf16<<<NWQ / 1024, 256>>>(Wo, wohi, wolo, NWQ);

    gemm_hmma<<<dim3(D_MODEL / 128, M_ROWS / 128), 256, GEMM_SMEM>>>(xhi, xlo, wqhi, wqlo, Q, D_MODEL);
    gemm_hmma<<<dim3(KV_DIM  / 128, M_ROWS / 128), 256, GEMM_SMEM>>>(xhi, xlo, wkhi, wklo, K, KV_DIM);
    gemm_hmma<<<dim3(KV_DIM  / 128, M_ROWS / 128), 256, GEMM_SMEM>>>(xhi, xlo, wvhi, wvlo, V, KV_DIM);

    attn_hmma<<<dim3(T_SEQ / 64, N_HEADS, BATCH), 128, ATTN_SMEM>>>(Q, K, V, AO);

    split_bf16<<<NX / 1024, 256>>>(AO, aohi, aolo, NX);
    gemm_hmma<<<dim3(D_MODEL / 128, M_ROWS / 128), 256, GEMM_SMEM>>>(aohi, aolo, wohi, wolo, out, D_MODEL);
}

// round 7
// speedup vs baseline: 3.9750x; 1.4481x over previous
#include <cuda_runtime.h>
#include <cuda_bf16.h>
#include <cuda_fp16.h>
#include <math.h>
#include <cstdint>

#define D_MODEL 2048
#define T_SEQ   2048
#define BATCH   2
#define N_HEADS 32
#define N_KV    8
#define D_KH    64
#define KV_DIM  (N_KV * D_KH)      // 512
#define M_ROWS  (BATCH * T_SEQ)    // 4096
#define GK      2048

// ---------------------------------------------------------------------------
// Scratch (__device__ globals; allocation-free rule)
// ---------------------------------------------------------------------------
__device__ float g_Q [M_ROWS * D_MODEL];
__device__ float g_K [M_ROWS * KV_DIM];
__device__ float g_V [M_ROWS * KV_DIM];
__device__ float g_AO[M_ROWS * D_MODEL];

__device__ __half g_xh  [M_ROWS * D_MODEL];
__device__ __half g_aoh [M_ROWS * D_MODEL];
__device__ __half g_wqh [D_MODEL * D_MODEL];
__device__ __half g_wql [D_MODEL * D_MODEL];
__device__ __half g_wkh [KV_DIM * D_MODEL];
__device__ __half g_wkl [KV_DIM * D_MODEL];
__device__ __half g_wvh [KV_DIM * D_MODEL];
__device__ __half g_wvl [KV_DIM * D_MODEL];
__device__ __half g_woh [D_MODEL * D_MODEL];
__device__ __half g_wol [D_MODEL * D_MODEL];

// ---------------------------------------------------------------------------
// Helpers
// ---------------------------------------------------------------------------
__device__ __forceinline__ uint32_t smem_u32(const void* p) {
    uint32_t a;
    asm("{ .reg .u64 t; cvta.to.shared.u64 t, %1; cvt.u32.u64 %0, t; }" : "=r"(a) : "l"(p));
    return a;
}
#define CP_ASYNC16(dst, src) \
    asm volatile("cp.async.cg.shared.global [%0], [%1], 16;" :: "r"(dst), "l"(src) : "memory")
#define CP_COMMIT() asm volatile("cp.async.commit_group;" ::: "memory")
#define CP_WAIT1()  asm volatile("cp.async.wait_group 1;" ::: "memory")

__device__ __forceinline__ void ldsm_x4(uint32_t& r0, uint32_t& r1, uint32_t& r2, uint32_t& r3, uint32_t a) {
    asm volatile("ldmatrix.sync.aligned.m8n8.x4.shared.b16 {%0,%1,%2,%3}, [%4];"
                 : "=r"(r0), "=r"(r1), "=r"(r2), "=r"(r3) : "r"(a));
}
__device__ __forceinline__ void ldsm_x4_t(uint32_t& r0, uint32_t& r1, uint32_t& r2, uint32_t& r3, uint32_t a) {
    asm volatile("ldmatrix.sync.aligned.m8n8.x4.trans.shared.b16 {%0,%1,%2,%3}, [%4];"
                 : "=r"(r0), "=r"(r1), "=r"(r2), "=r"(r3) : "r"(a));
}
__device__ __forceinline__ void ldsm_x2(uint32_t& r0, uint32_t& r1, uint32_t a) {
    asm volatile("ldmatrix.sync.aligned.m8n8.x2.shared.b16 {%0,%1}, [%2];"
                 : "=r"(r0), "=r"(r1) : "r"(a));
}
__device__ __forceinline__ void mma_f16(float* c, const uint32_t* a, const uint32_t* b) {
    asm volatile("mma.sync.aligned.m16n8k16.row.col.f32.f16.f16.f32 "
                 "{%0,%1,%2,%3}, {%4,%5,%6,%7}, {%8,%9}, {%0,%1,%2,%3};"
                 : "+f"(c[0]), "+f"(c[1]), "+f"(c[2]), "+f"(c[3])
                 : "r"(a[0]), "r"(a[1]), "r"(a[2]), "r"(a[3]), "r"(b[0]), "r"(b[1]));
}
__device__ __forceinline__ uint32_t pack_f16(float lo, float hi) {
    uint32_t r;
    asm("cvt.rn.f16x2.f32 %0, %1, %2;" : "=r"(r) : "f"(hi), "f"(lo));
    return r;
}
__device__ __forceinline__ float f16_round(float v) {
    return __half2float(__float2half_rn(v));
}

// ---------------------------------------------------------------------------
// Conversions
// ---------------------------------------------------------------------------
__global__ __launch_bounds__(256) void to_f16(
    const float* __restrict__ s, __half* __restrict__ d, int n)
{
    int i = (blockIdx.x * 256 + threadIdx.x) * 4;
    if (i >= n) return;
    float4 v = *(const float4*)(s + i);
    *(uint2*)(d + i) = make_uint2(pack_f16(v.x, v.y), pack_f16(v.z, v.w));
}

__global__ __launch_bounds__(256) void split_f16(
    const float* __restrict__ s, __half* __restrict__ hi,
    __half* __restrict__ lo, int n)
{
    int i = (blockIdx.x * 256 + threadIdx.x) * 4;
    if (i >= n) return;
    float4 v = *(const float4*)(s + i);
    float h0 = f16_round(v.x), h1 = f16_round(v.y), h2 = f16_round(v.z), h3 = f16_round(v.w);
    *(uint2*)(hi + i) = make_uint2(pack_f16(h0, h1), pack_f16(h2, h3));
    *(uint2*)(lo + i) = make_uint2(pack_f16(v.x - h0, v.y - h1), pack_f16(v.z - h2, v.w - h3));
}

// ---------------------------------------------------------------------------
// HMMA GEMM: Y[M,N] = A[M,2048] @ B[N,2048]^T
// A: fp16 (hi only). B: fp16 hi+lo (2-term split).
// CTA 128x128, BK=32, 8 warps, cp.async double buffer. 80B smem rows.
// ---------------------------------------------------------------------------
#define RS      80
#define TILE_B  (128 * RS)            // 10240
#define STG_B   (3 * TILE_B)          // 30720
#define GEMM_SMEM (2 * STG_B)         // 61440

__global__ __launch_bounds__(256) void gemm_hmma(
    const __half* __restrict__ Ah, const __half* __restrict__ Bh,
    const __half* __restrict__ Bl, float* __restrict__ Y, int N)
{
    extern __shared__ __align__(128) char smem[];
    const uint32_t sb = smem_u32(smem);

    const int t   = threadIdx.x;
    const int wid = t >> 5, l = t & 31;
    const int wm  = wid & 1, wn = wid >> 1;
    const int bm  = blockIdx.y * 128, bn = blockIdx.x * 128;

    const __half* srcs[3] = {Ah + (size_t)bm * GK, Bh + (size_t)bn * GK, Bl + (size_t)bn * GK};

    int c_tile[6], c_dst[6];
    size_t c_src[6];
#pragma unroll
    for (int c = 0; c < 6; c++) {
        int chunk = t + c * 256;          // 1536 chunks = 3 tiles x 512
        int tile = chunk >> 9;
        int idx  = chunk & 511;
        int row  = idx >> 2;
        int k16  = idx & 3;
        c_tile[c] = tile;
        c_dst[c]  = tile * TILE_B + row * RS + k16 * 16;
        c_src[c]  = (size_t)row * GK + k16 * 8;
    }

    auto load_stage = [&](int s, int k0) {
        uint32_t base = sb + s * STG_B;
#pragma unroll
        for (int c = 0; c < 6; c++)
            CP_ASYNC16(base + c_dst[c], (const char*)(srcs[c_tile[c]] + k0 + c_src[c]));
    };

    float acc[4][4][4];
#pragma unroll
    for (int i = 0; i < 4; i++)
#pragma unroll
        for (int j = 0; j < 4; j++)
#pragma unroll
            for (int k = 0; k < 4; k++) acc[i][j][k] = 0.f;

    const uint32_t aBase = sb + (uint32_t)((wm * 64 + (l & 15)) * RS + (l >> 4) * 16);
    const uint32_t bBase = sb + TILE_B + (uint32_t)((wn * 32 + (l & 7)) * RS + ((l & 15) >> 3) * 16);

    const int nIter = GK / 32;
    load_stage(0, 0);
    CP_COMMIT();

    for (int it = 0; it < nIter; it++) {
        if (it + 1 < nIter) load_stage((it + 1) & 1, (it + 1) * 32);
        CP_COMMIT();
        CP_WAIT1();
        __syncthreads();

        const uint32_t so = (uint32_t)((it & 1) * STG_B);
#pragma unroll
        for (int ks = 0; ks < 2; ks++) {
            const uint32_t kb = so + ks * 32;
            uint32_t ah[4][4], bh[4][2], bl[4][2];
#pragma unroll
            for (int mt = 0; mt < 4; mt++) {
                uint32_t a = aBase + kb + mt * 16 * RS;
                ldsm_x4(ah[mt][0], ah[mt][1], ah[mt][2], ah[mt][3], a);
            }
#pragma unroll
            for (int nt = 0; nt < 4; nt++) {
                uint32_t a = bBase + kb + nt * 8 * RS;
                ldsm_x2(bh[nt][0], bh[nt][1], a);
                ldsm_x2(bl[nt][0], bl[nt][1], a + TILE_B);
            }
#pragma unroll
            for (int mt = 0; mt < 4; mt++)
#pragma unroll
                for (int nt = 0; nt < 4; nt++) {
                    mma_f16(acc[mt][nt], ah[mt], bh[nt]);
                    mma_f16(acc[mt][nt], ah[mt], bl[nt]);
                }
        }
        __syncthreads();
    }

    const int r0c = bm + wm * 64 + (l >> 2);
    const int col0 = bn + wn * 32 + (l & 3) * 2;
#pragma unroll
    for (int mt = 0; mt < 4; mt++) {
#pragma unroll
        for (int nt = 0; nt < 4; nt++) {
            float* y0 = Y + (size_t)(r0c + mt * 16) * N + col0 + nt * 8;
            float* y1 = y0 + 8 * N;
            y0[0] = acc[mt][nt][0]; y0[1] = acc[mt][nt][1];
            y1[0] = acc[mt][nt][2]; y1[1] = acc[mt][nt][3];
        }
    }
}

// ---------------------------------------------------------------------------
// HMMA flash attention, causal GQA, fp16 2-term precision scheme.
// Tiles: Qh (hi only), Kh+Kl (split), Vh (hi only); P split in registers.
// CTA: 64 q-rows x one (b,h). 128 threads = 4 warps.
// ---------------------------------------------------------------------------
#define ATS  72
#define ATSB (64 * ATS * 2)             // 9216
#define ATTN_SMEM (4 * ATSB)            // 36864

__global__ __launch_bounds__(128) void attn_hmma(
    const float* __restrict__ Q, const float* __restrict__ K,
    const float* __restrict__ V, float* __restrict__ O)
{
    extern __shared__ __align__(128) char smem[];
    const uint32_t sb  = smem_u32(smem);
    const uint32_t qh_ = sb;
    const uint32_t kh_ = sb + ATSB;
    const uint32_t kl_ = sb + 2 * ATSB;
    const uint32_t vh_ = sb + 3 * ATSB;

    const int qt = blockIdx.x;
    const int h  = blockIdx.y;
    const int b  = blockIdx.z;
    const int kv = h >> 2;

    const int t = threadIdx.x;
    const int w = t >> 5, l = t & 31;
    const float scale = 0.125f;

    // ---- Stage Q tile (fp32 -> fp16 hi) ----
    const float* Qg = Q + ((size_t)(b * T_SEQ + qt * 64)) * D_MODEL + h * D_KH;
#pragma unroll
    for (int i = 0; i < 8; i++) {
        int idx = i * 128 + t;
        int row = idx >> 4;
        int c4  = (idx & 15) * 4;
        float4 v = *(const float4*)(Qg + (size_t)row * D_MODEL + c4);
        uint32_t off = (uint32_t)(row * (ATS * 2) + c4 * 2);
        *(uint2*)(smem + off) = make_uint2(pack_f16(v.x, v.y), pack_f16(v.z, v.w));
    }
    __syncthreads();

    uint32_t aq[4][4];
#pragma unroll
    for (int kc = 0; kc < 4; kc++) {
        uint32_t a = qh_ + (uint32_t)((w * 16 + (l & 15)) * (ATS * 2) + kc * 32 + (l >> 4) * 16);
        ldsm_x4(aq[kc][0], aq[kc][1], aq[kc][2], aq[kc][3], a);
    }

    float o[8][4];
#pragma unroll
    for (int i = 0; i < 8; i++)
#pragma unroll
        for (int j = 0; j < 4; j++) o[i][j] = 0.f;
    float m0 = -1e30f, m1 = -1e30f, l0 = 0.f, l1 = 0.f;

    for (int kt = 0; kt <= qt; kt++) {
        __syncthreads();
        // ---- Stage K (hi+lo) and V (hi) ----
        const float* Kg = K + ((size_t)(b * T_SEQ + kt * 64)) * KV_DIM + kv * D_KH;
        const float* Vg = V + ((size_t)(b * T_SEQ + kt * 64)) * KV_DIM + kv * D_KH;
#pragma unroll
        for (int i = 0; i < 8; i++) {
            int idx = i * 128 + t;
            int row = idx >> 4;
            int c4  = (idx & 15) * 4;
            uint32_t off = (uint32_t)(row * (ATS * 2) + c4 * 2);
            float4 kx = *(const float4*)(Kg + (size_t)row * KV_DIM + c4);
            float k0 = f16_round(kx.x), k1 = f16_round(kx.y), k2 = f16_round(kx.z), k3 = f16_round(kx.w);
            *(uint2*)(smem + (kh_ - sb) + off) = make_uint2(pack_f16(k0, k1), pack_f16(k2, k3));
            *(uint2*)(smem + (kl_ - sb) + off) = make_uint2(pack_f16(kx.x - k0, kx.y - k1),
                                                            pack_f16(kx.z - k2, kx.w - k3));
            float4 vx = *(const float4*)(Vg + (size_t)row * KV_DIM + c4);
            *(uint2*)(smem + (vh_ - sb) + off) = make_uint2(pack_f16(vx.x, vx.y), pack_f16(vx.z, vx.w));
        }
        __syncthreads();

        // ---- S = Q @ K^T  (Qh·Kh + Qh·Kl) ----
        float s[8][4];
#pragma unroll
        for (int i = 0; i < 8; i++)
#pragma unroll
            for (int j = 0; j < 4; j++) s[i][j] = 0.f;

#pragma unroll
        for (int nt = 0; nt < 8; nt++) {
#pragma unroll
            for (int kcp = 0; kcp < 2; kcp++) {
                uint32_t a = kh_ + (uint32_t)((nt * 8 + (l & 7)) * (ATS * 2) + kcp * 64 + (l >> 3) * 16);
                uint32_t h0, h1, h2, h3, g0, g1, g2, g3;
                ldsm_x4(h0, h1, h2, h3, a);
                ldsm_x4(g0, g1, g2, g3, a + ATSB);
                uint32_t bh0[2] = {h0, h1}, bh1[2] = {h2, h3};
                uint32_t bl0[2] = {g0, g1}, bl1[2] = {g2, g3};
                mma_f16(s[nt], aq[2 * kcp],     bh0);
                mma_f16(s[nt], aq[2 * kcp],     bl0);
                mma_f16(s[nt], aq[2 * kcp + 1], bh1);
                mma_f16(s[nt], aq[2 * kcp + 1], bl1);
            }
        }

        // ---- scale + causal mask ----
        const int rl0 = w * 16 + (l >> 2);
        const bool diag = (kt == qt);
#pragma unroll
        for (int nt = 0; nt < 8; nt++) {
            int c0 = nt * 8 + (l & 3) * 2;
#pragma unroll
            for (int j = 0; j < 4; j++) {
                float v = s[nt][j] * scale;
                int c = c0 + (j & 1);
                int r = rl0 + ((j >> 1) << 3);
                if (diag && c > r) v = -1e30f;
                s[nt][j] = v;
            }
        }

        // ---- register online softmax ----
        float mx0 = -1e30f, mx1 = -1e30f;
#pragma unroll
        for (int nt = 0; nt < 8; nt++) {
            mx0 = fmaxf(mx0, fmaxf(s[nt][0], s[nt][1]));
            mx1 = fmaxf(mx1, fmaxf(s[nt][2], s[nt][3]));
        }
        mx0 = fmaxf(mx0, __shfl_xor_sync(0xffffffff, mx0, 1));
        mx0 = fmaxf(mx0, __shfl_xor_sync(0xffffffff, mx0, 2));
        mx1 = fmaxf(mx1, __shfl_xor_sync(0xffffffff, mx1, 1));
        mx1 = fmaxf(mx1, __shfl_xor_sync(0xffffffff, mx1, 2));

        float mn0 = fmaxf(m0, mx0), mn1 = fmaxf(m1, mx1);
        float al0 = __expf(m0 - mn0), al1 = __expf(m1 - mn1);
        m0 = mn0; m1 = mn1;

        float sum0 = 0.f, sum1 = 0.f;
#pragma unroll
        for (int nt = 0; nt < 8; nt++) {
            s[nt][0] = __expf(s[nt][0] - mn0); sum0 += s[nt][0];
            s[nt][1] = __expf(s[nt][1] - mn0); sum0 += s[nt][1];
            s[nt][2] = __expf(s[nt][2] - mn1); sum1 += s[nt][2];
            s[nt][3] = __expf(s[nt][3] - mn1); sum1 += s[nt][3];
        }
        sum0 += __shfl_xor_sync(0xffffffff, sum0, 1);
        sum0 += __shfl_xor_sync(0xffffffff, sum0, 2);
        sum1 += __shfl_xor_sync(0xffffffff, sum1, 1);
        sum1 += __shfl_xor_sync(0xffffffff, sum1, 2);
        l0 = l0 * al0 + sum0;
        l1 = l1 * al1 + sum1;

#pragma unroll
        for (int nt = 0; nt < 8; nt++) {
            o[nt][0] *= al0; o[nt][1] *= al0;
            o[nt][2] *= al1; o[nt][3] *= al1;
        }

        // ---- O += P @ V  ((Ph+Pl)·Vh; P split in registers) ----
#pragma unroll
        for (int kc2 = 0; kc2 < 4; kc2++) {
            float p00 = s[2 * kc2][0],     p01 = s[2 * kc2][1];
            float p02 = s[2 * kc2][2],     p03 = s[2 * kc2][3];
            float p10 = s[2 * kc2 + 1][0], p11 = s[2 * kc2 + 1][1];
            float p12 = s[2 * kc2 + 1][2], p13 = s[2 * kc2 + 1][3];
            float q00 = f16_round(p00), q01 = f16_round(p01), q02 = f16_round(p02), q03 = f16_round(p03);
            float q10 = f16_round(p10), q11 = f16_round(p11), q12 = f16_round(p12), q13 = f16_round(p13);
            uint32_t aph[4] = {pack_f16(q00, q01), pack_f16(q02, q03),
                               pack_f16(q10, q11), pack_f16(q12, q13)};
            uint32_t apl[4] = {pack_f16(p00 - q00, p01 - q01), pack_f16(p02 - q02, p03 - q03),
                               pack_f16(p10 - q10, p11 - q11), pack_f16(p12 - q12, p13 - q13)};
#pragma unroll
            for (int ntp = 0; ntp < 4; ntp++) {
                uint32_t a = vh_ + (uint32_t)((kc2 * 16 + (l & 15)) * (ATS * 2) + ntp * 32 + (l >> 4) * 16);
                uint32_t h0, h1, h2, h3;
                ldsm_x4_t(h0, h1, h2, h3, a);
                uint32_t bh0[2] = {h0, h1}, bh1[2] = {h2, h3};
                mma_f16(o[2 * ntp],     aph, bh0);
                mma_f16(o[2 * ntp],     apl, bh0);
                mma_f16(o[2 * ntp + 1], aph, bh1);
                mma_f16(o[2 * ntp + 1], apl, bh1);
            }
        }
    }

    // ---- epilogue ----
    const float il0 = 1.0f / l0, il1 = 1.0f / l1;
    const size_t row0 = (size_t)(b * T_SEQ + qt * 64 + w * 16 + (l >> 2));
    float* Ob = O + row0 * D_MODEL + h * D_KH + (l & 3) * 2;
#pragma unroll
    for (int nt = 0; nt < 8; nt++) {
        *(float2*)(Ob + nt * 8)               = make_float2(o[nt][0] * il0, o[nt][1] * il0);
        *(float2*)(Ob + nt * 8 + 8 * D_MODEL) = make_float2(o[nt][2] * il1, o[nt][3] * il1);
    }
}

// ---------------------------------------------------------------------------
// Launch
// ---------------------------------------------------------------------------
extern "C" void kernel_launch(void* const* d_in, const int* in_sizes, int n_in,
                              void* d_out, int out_size)
{
    const float* x  = (const float*)d_in[0];
    const float* Wq = (const float*)d_in[1];
    const float* Wk = (const float*)d_in[2];
    const float* Wv = (const float*)d_in[3];
    const float* Wo = (const float*)d_in[4];
    float* out = (float*)d_out;

    float *Q, *K, *V, *AO;
    cudaGetSymbolAddress((void**)&Q,  g_Q);
    cudaGetSymbolAddress((void**)&K,  g_K);
    cudaGetSymbolAddress((void**)&V,  g_V);
    cudaGetSymbolAddress((void**)&AO, g_AO);

    __half *xh, *aoh, *wqh, *wql, *wkh, *wkl, *wvh, *wvl, *woh, *wol;
    cudaGetSymbolAddress((void**)&xh,  g_xh);
    cudaGetSymbolAddress((void**)&aoh, g_aoh);
    cudaGetSymbolAddress((void**)&wqh, g_wqh); cudaGetSymbolAddress((void**)&wql, g_wql);
    cudaGetSymbolAddress((void**)&wkh, g_wkh); cudaGetSymbolAddress((void**)&wkl, g_wkl);
    cudaGetSymbolAddress((void**)&wvh, g_wvh); cudaGetSymbolAddress((void**)&wvl, g_wvl);
    cudaGetSymbolAddress((void**)&woh, g_woh); cudaGetSymbolAddress((void**)&wol, g_wol);

    cudaFuncSetAttribute(gemm_hmma, cudaFuncAttributeMaxDynamicSharedMemorySize, GEMM_SMEM);
    cudaFuncSetAttribute(attn_hmma, cudaFuncAttributeMaxDynamicSharedMemorySize, ATTN_SMEM);

    const int NX  = M_ROWS * D_MODEL;
    const int NWQ = D_MODEL * D_MODEL;
    const int NWK = KV_DIM * D_MODEL;

    to_f16  <<<NX  / 1024, 256>>>(x,  xh,  NX);
    split_f16<<<NWQ / 1024, 256>>>(Wq, wqh, wql, NWQ);
    split_f16<<<NWK / 1024, 256>>>(Wk, wkh, wkl, NWK);
    split_f16<<<NWK / 1024, 256>>>(Wv, wvh, wvl, NWK);
    split_f16<<<NWQ / 1024, 256>>>(Wo, woh, wol, NWQ);

    gemm_hmma<<<dim3(D_MODEL / 128, M_ROWS / 128), 256, GEMM_SMEM>>>(xh, wqh, wql, Q, D_MODEL);
    gemm_hmma<<<dim3(KV_DIM  / 128, M_ROWS / 128), 256, GEMM_SMEM>>>(xh, wkh, wkl, K, KV_DIM);
    gemm_hmma<<<dim3(KV_DIM  / 128, M_ROWS / 128), 256, GEMM_SMEM>>>(xh, wvh, wvl, V, KV_DIM);

    attn_hmma<<<dim3(T_SEQ / 64, N_HEADS, BATCH), 128, ATTN_SMEM>>>(Q, K, V, AO);

    to_f16<<<NX / 1024, 256>>>(AO, aoh, NX);
    gemm_hmma<<<dim3(D_MODEL / 128, M_ROWS / 128), 256, GEMM_SMEM>>>(aoh, woh, wol, out, D_MODEL);
}

// round 11
// speedup vs baseline: 4.1305x; 1.0391x over previous
#include <cuda_runtime.h>
#include <cuda_fp16.h>
#include <math.h>
#include <cstdint>

#define D_MODEL 2048
#define T_SEQ   2048
#define BATCH   2
#define N_HEADS 32
#define N_KV    8
#define D_KH    64
#define KV_DIM  (N_KV * D_KH)      // 512
#define M_ROWS  (BATCH * T_SEQ)    // 4096
#define GK      2048
#define NWQ     (D_MODEL * D_MODEL)
#define NWK     (KV_DIM * D_MODEL)

// ---------------------------------------------------------------------------
// Scratch (__device__ globals; allocation-free rule)
// ---------------------------------------------------------------------------
__device__ __half g_xh [M_ROWS * D_MODEL];
__device__ __half g_qh [M_ROWS * D_MODEL];     // Q fp16 hi
__device__ __half g_kh [M_ROWS * KV_DIM];      // K fp16 hi
__device__ __half g_kl [M_ROWS * KV_DIM];      // K fp16 lo
__device__ __half g_vh [M_ROWS * KV_DIM];      // V fp16 hi
__device__ __half g_aoh[M_ROWS * D_MODEL];     // attention out fp16

__device__ __half g_wqh[NWQ], g_wql[NWQ];
__device__ __half g_wkh[NWK], g_wkl[NWK];
__device__ __half g_wvh[NWK], g_wvl[NWK];
__device__ __half g_woh[NWQ], g_wol[NWQ];

// ---------------------------------------------------------------------------
// Helpers
// ---------------------------------------------------------------------------
__device__ __forceinline__ uint32_t smem_u32(const void* p) {
    uint32_t a;
    asm("{ .reg .u64 t; cvta.to.shared.u64 t, %1; cvt.u32.u64 %0, t; }" : "=r"(a) : "l"(p));
    return a;
}
#define CP_ASYNC16(dst, src) \
    asm volatile("cp.async.cg.shared.global [%0], [%1], 16;" :: "r"(dst), "l"(src) : "memory")
#define CP_COMMIT() asm volatile("cp.async.commit_group;" ::: "memory")
#define CP_WAIT1()  asm volatile("cp.async.wait_group 1;" ::: "memory")

__device__ __forceinline__ void ldsm_x4(uint32_t& r0, uint32_t& r1, uint32_t& r2, uint32_t& r3, uint32_t a) {
    asm volatile("ldmatrix.sync.aligned.m8n8.x4.shared.b16 {%0,%1,%2,%3}, [%4];"
                 : "=r"(r0), "=r"(r1), "=r"(r2), "=r"(r3) : "r"(a));
}
__device__ __forceinline__ void ldsm_x4_t(uint32_t& r0, uint32_t& r1, uint32_t& r2, uint32_t& r3, uint32_t a) {
    asm volatile("ldmatrix.sync.aligned.m8n8.x4.trans.shared.b16 {%0,%1,%2,%3}, [%4];"
                 : "=r"(r0), "=r"(r1), "=r"(r2), "=r"(r3) : "r"(a));
}
__device__ __forceinline__ void ldsm_x2(uint32_t& r0, uint32_t& r1, uint32_t a) {
    asm volatile("ldmatrix.sync.aligned.m8n8.x2.shared.b16 {%0,%1}, [%2];"
                 : "=r"(r0), "=r"(r1) : "r"(a));
}
__device__ __forceinline__ void mma_f16(float* c, const uint32_t* a, const uint32_t* b) {
    asm volatile("mma.sync.aligned.m16n8k16.row.col.f32.f16.f16.f32 "
                 "{%0,%1,%2,%3}, {%4,%5,%6,%7}, {%8,%9}, {%0,%1,%2,%3};"
                 : "+f"(c[0]), "+f"(c[1]), "+f"(c[2]), "+f"(c[3])
                 : "r"(a[0]), "r"(a[1]), "r"(a[2]), "r"(a[3]), "r"(b[0]), "r"(b[1]));
}
__device__ __forceinline__ uint32_t pack_f16(float lo, float hi) {
    uint32_t r;
    asm("cvt.rn.f16x2.f32 %0, %1, %2;" : "=r"(r) : "f"(hi), "f"(lo));
    return r;
}
__device__ __forceinline__ float f16_round(float v) {
    return __half2float(__float2half_rn(v));
}

// ---------------------------------------------------------------------------
// Conversions
// ---------------------------------------------------------------------------
__global__ __launch_bounds__(256) void to_f16(
    const float* __restrict__ s, __half* __restrict__ d, int n)
{
    int i = (blockIdx.x * 256 + threadIdx.x) * 4;
    if (i >= n) return;
    float4 v = *(const float4*)(s + i);
    *(uint2*)(d + i) = make_uint2(pack_f16(v.x, v.y), pack_f16(v.z, v.w));
}

// All four weight splits in one launch.
__global__ __launch_bounds__(256) void split_weights(
    const float* __restrict__ wq, const float* __restrict__ wk,
    const float* __restrict__ wv, const float* __restrict__ wo,
    __half* __restrict__ qh, __half* __restrict__ ql,
    __half* __restrict__ kh, __half* __restrict__ kl,
    __half* __restrict__ vh, __half* __restrict__ vl,
    __half* __restrict__ oh, __half* __restrict__ ol)
{
    int e = (blockIdx.x * 256 + threadIdx.x) * 4;
    const float* s; __half *hi, *lo;
    if (e < NWQ)                 { s = wq; hi = qh; lo = ql; }
    else if (e < NWQ + NWK)      { s = wk; hi = kh; lo = kl; e -= NWQ; }
    else if (e < NWQ + 2 * NWK)  { s = wv; hi = vh; lo = vl; e -= NWQ + NWK; }
    else                         { s = wo; hi = oh; lo = ol; e -= NWQ + 2 * NWK; }
    float4 v = *(const float4*)(s + e);
    float h0 = f16_round(v.x), h1 = f16_round(v.y), h2 = f16_round(v.z), h3 = f16_round(v.w);
    *(uint2*)(hi + e) = make_uint2(pack_f16(h0, h1), pack_f16(h2, h3));
    *(uint2*)(lo + e) = make_uint2(pack_f16(v.x - h0, v.y - h1), pack_f16(v.z - h2, v.w - h3));
}

// ---------------------------------------------------------------------------
// Merged QKV GEMM: A=xh [4096,2048] fp16. B per region (Wq/Wk/Wv hi+lo).
// Writes fp16 outputs: Q hi; K hi+lo; V hi.
// CTA 128x128, BK=32, 8 warps, cp.async double buffer, 80B rows.
// ---------------------------------------------------------------------------
#define RS      80
#define TILE_B  (128 * RS)
#define STG_B   (3 * TILE_B)
#define GEMM_SMEM (2 * STG_B)

__global__ __launch_bounds__(256) void gemm_qkv(
    const __half* __restrict__ Ah,
    const __half* __restrict__ Wqh, const __half* __restrict__ Wql,
    const __half* __restrict__ Wkh, const __half* __restrict__ Wkl,
    const __half* __restrict__ Wvh, const __half* __restrict__ Wvl,
    __half* __restrict__ Qo, __half* __restrict__ Kho, __half* __restrict__ Klo,
    __half* __restrict__ Vo)
{
    extern __shared__ __align__(128) char smem[];
    const uint32_t sb = smem_u32(smem);

    const int t   = threadIdx.x;
    const int wid = t >> 5, l = t & 31;
    const int wm  = wid & 1, wn = wid >> 1;
    const int bx  = blockIdx.x;
    const int bm  = blockIdx.y * 128;

    // Region select
    const __half *Bh, *Bl;
    int mode, bcol;                 // 0=Q, 1=K, 2=V
    if (bx < 16)      { mode = 0; bcol = bx * 128;        Bh = Wqh; Bl = Wql; }
    else if (bx < 20) { mode = 1; bcol = (bx - 16) * 128; Bh = Wkh; Bl = Wkl; }
    else              { mode = 2; bcol = (bx - 20) * 128; Bh = Wvh; Bl = Wvl; }

    const __half* srcs[3] = {Ah + (size_t)bm * GK, Bh + (size_t)bcol * GK, Bl + (size_t)bcol * GK};

    int c_tile[6], c_dst[6];
    size_t c_src[6];
#pragma unroll
    for (int c = 0; c < 6; c++) {
        int chunk = t + c * 256;
        int tile = chunk >> 9;
        int idx  = chunk & 511;
        int row  = idx >> 2;
        int k16  = idx & 3;
        c_tile[c] = tile;
        c_dst[c]  = tile * TILE_B + row * RS + k16 * 16;
        c_src[c]  = (size_t)row * GK + k16 * 8;
    }

    auto load_stage = [&](int s, int k0) {
        uint32_t base = sb + s * STG_B;
#pragma unroll
        for (int c = 0; c < 6; c++)
            CP_ASYNC16(base + c_dst[c], (const char*)(srcs[c_tile[c]] + k0 + c_src[c]));
    };

    float acc[4][4][4];
#pragma unroll
    for (int i = 0; i < 4; i++)
#pragma unroll
        for (int j = 0; j < 4; j++)
#pragma unroll
            for (int k = 0; k < 4; k++) acc[i][j][k] = 0.f;

    const uint32_t aBase = sb + (uint32_t)((wm * 64 + (l & 15)) * RS + (l >> 4) * 16);
    const uint32_t bBase = sb + TILE_B + (uint32_t)((wn * 32 + (l & 7)) * RS + ((l & 15) >> 3) * 16);

    const int nIter = GK / 32;
    load_stage(0, 0);
    CP_COMMIT();

    for (int it = 0; it < nIter; it++) {
        if (it + 1 < nIter) load_stage((it + 1) & 1, (it + 1) * 32);
        CP_COMMIT();
        CP_WAIT1();
        __syncthreads();

        const uint32_t so = (uint32_t)((it & 1) * STG_B);
#pragma unroll
        for (int ks = 0; ks < 2; ks++) {
            const uint32_t kb = so + ks * 32;
            uint32_t ah[4][4], bh[4][2], bl[4][2];
#pragma unroll
            for (int mt = 0; mt < 4; mt++) {
                uint32_t a = aBase + kb + mt * 16 * RS;
                ldsm_x4(ah[mt][0], ah[mt][1], ah[mt][2], ah[mt][3], a);
            }
#pragma unroll
            for (int nt = 0; nt < 4; nt++) {
                uint32_t a = bBase + kb + nt * 8 * RS;
                ldsm_x2(bh[nt][0], bh[nt][1], a);
                ldsm_x2(bl[nt][0], bl[nt][1], a + TILE_B);
            }
#pragma unroll
            for (int mt = 0; mt < 4; mt++)
#pragma unroll
                for (int nt = 0; nt < 4; nt++) {
                    mma_f16(acc[mt][nt], ah[mt], bh[nt]);
                    mma_f16(acc[mt][nt], ah[mt], bl[nt]);
                }
        }
        __syncthreads();
    }

    // Epilogue: fp16 writes
    const int r0c = bm + wm * 64 + (l >> 2);
    const int colr = bcol + wn * 32 + (l & 3) * 2;     // region-relative column
    const int stride = (mode == 0) ? D_MODEL : KV_DIM;
#pragma unroll
    for (int mt = 0; mt < 4; mt++) {
#pragma unroll
        for (int nt = 0; nt < 4; nt++) {
            size_t o0 = (size_t)(r0c + mt * 16) * stride + colr + nt * 8;
            size_t o1 = o0 + 8 * stride;
            float a0 = acc[mt][nt][0], a1 = acc[mt][nt][1];
            float a2 = acc[mt][nt][2], a3 = acc[mt][nt][3];
            if (mode == 0) {
                *(uint32_t*)(Qo + o0) = pack_f16(a0, a1);
                *(uint32_t*)(Qo + o1) = pack_f16(a2, a3);
            } else if (mode == 2) {
                *(uint32_t*)(Vo + o0) = pack_f16(a0, a1);
                *(uint32_t*)(Vo + o1) = pack_f16(a2, a3);
            } else {
                float h0 = f16_round(a0), h1 = f16_round(a1);
                float h2 = f16_round(a2), h3 = f16_round(a3);
                *(uint32_t*)(Kho + o0) = pack_f16(h0, h1);
                *(uint32_t*)(Kho + o1) = pack_f16(h2, h3);
                *(uint32_t*)(Klo + o0) = pack_f16(a0 - h0, a1 - h1);
                *(uint32_t*)(Klo + o1) = pack_f16(a2 - h2, a3 - h3);
            }
        }
    }
}

// ---------------------------------------------------------------------------
// Wo GEMM: fp32 output to harness buffer (same core as gemm_qkv, fp32 epilogue)
// ---------------------------------------------------------------------------
__global__ __launch_bounds__(256) void gemm_out(
    const __half* __restrict__ Ah, const __half* __restrict__ Bh,
    const __half* __restrict__ Bl, float* __restrict__ Y)
{
    extern __shared__ __align__(128) char smem[];
    const uint32_t sb = smem_u32(smem);

    const int t   = threadIdx.x;
    const int wid = t >> 5, l = t & 31;
    const int wm  = wid & 1, wn = wid >> 1;
    const int bm  = blockIdx.y * 128, bn = blockIdx.x * 128;

    const __half* srcs[3] = {Ah + (size_t)bm * GK, Bh + (size_t)bn * GK, Bl + (size_t)bn * GK};

    int c_tile[6], c_dst[6];
    size_t c_src[6];
#pragma unroll
    for (int c = 0; c < 6; c++) {
        int chunk = t + c * 256;
        int tile = chunk >> 9;
        int idx  = chunk & 511;
        int row  = idx >> 2;
        int k16  = idx & 3;
        c_tile[c] = tile;
        c_dst[c]  = tile * TILE_B + row * RS + k16 * 16;
        c_src[c]  = (size_t)row * GK + k16 * 8;
    }

    auto load_stage = [&](int s, int k0) {
        uint32_t base = sb + s * STG_B;
#pragma unroll
        for (int c = 0; c < 6; c++)
            CP_ASYNC16(base + c_dst[c], (const char*)(srcs[c_tile[c]] + k0 + c_src[c]));
    };

    float acc[4][4][4];
#pragma unroll
    for (int i = 0; i < 4; i++)
#pragma unroll
        for (int j = 0; j < 4; j++)
#pragma unroll
            for (int k = 0; k < 4; k++) acc[i][j][k] = 0.f;

    const uint32_t aBase = sb + (uint32_t)((wm * 64 + (l & 15)) * RS + (l >> 4) * 16);
    const uint32_t bBase = sb + TILE_B + (uint32_t)((wn * 32 + (l & 7)) * RS + ((l & 15) >> 3) * 16);

    const int nIter = GK / 32;
    load_stage(0, 0);
    CP_COMMIT();

    for (int it = 0; it < nIter; it++) {
        if (it + 1 < nIter) load_stage((it + 1) & 1, (it + 1) * 32);
        CP_COMMIT();
        CP_WAIT1();
        __syncthreads();

        const uint32_t so = (uint32_t)((it & 1) * STG_B);
#pragma unroll
        for (int ks = 0; ks < 2; ks++) {
            const uint32_t kb = so + ks * 32;
            uint32_t ah[4][4], bh[4][2], bl[4][2];
#pragma unroll
            for (int mt = 0; mt < 4; mt++) {
                uint32_t a = aBase + kb + mt * 16 * RS;
                ldsm_x4(ah[mt][0], ah[mt][1], ah[mt][2], ah[mt][3], a);
            }
#pragma unroll
            for (int nt = 0; nt < 4; nt++) {
                uint32_t a = bBase + kb + nt * 8 * RS;
                ldsm_x2(bh[nt][0], bh[nt][1], a);
                ldsm_x2(bl[nt][0], bl[nt][1], a + TILE_B);
            }
#pragma unroll
            for (int mt = 0; mt < 4; mt++)
#pragma unroll
                for (int nt = 0; nt < 4; nt++) {
                    mma_f16(acc[mt][nt], ah[mt], bh[nt]);
                    mma_f16(acc[mt][nt], ah[mt], bl[nt]);
                }
        }
        __syncthreads();
    }

    const int r0c = bm + wm * 64 + (l >> 2);
    const int col0 = bn + wn * 32 + (l & 3) * 2;
#pragma unroll
    for (int mt = 0; mt < 4; mt++) {
#pragma unroll
        for (int nt = 0; nt < 4; nt++) {
            float* y0 = Y + (size_t)(r0c + mt * 16) * D_MODEL + col0 + nt * 8;
            float* y1 = y0 + 8 * D_MODEL;
            y0[0] = acc[mt][nt][0]; y0[1] = acc[mt][nt][1];
            y1[0] = acc[mt][nt][2]; y1[1] = acc[mt][nt][3];
        }
    }
}

// ---------------------------------------------------------------------------
// Flash attention: CTA = (qtile 64 rows) x (kv head) x batch; 4 query heads
// share K/V. 512 threads = 16 warps = 4 head-groups of 4 warps.
// Inputs pre-converted fp16 (Q hi, K hi+lo, V hi) -> pure cp.async staging.
// 3-stage KV pipeline. PV uses P-hi only. Output fp16.
// ---------------------------------------------------------------------------
#define ATS  72
#define ATSB (64 * ATS * 2)                 // 9216
#define ATTN_SMEM (13 * ATSB)               // 4 Q + 3x(kh,kl,vh) = 119808

__global__ __launch_bounds__(512, 1) void attn_hmma(
    const __half* __restrict__ Qh, const __half* __restrict__ Kh,
    const __half* __restrict__ Kl, const __half* __restrict__ Vh,
    __half* __restrict__ O)
{
    extern __shared__ __align__(128) char smem[];
    const uint32_t sb = smem_u32(smem);

    const int qt  = blockIdx.x;
    const int kvh = blockIdx.y;
    const int b   = blockIdx.z;

    const int t  = threadIdx.x;
    const int w5 = t >> 5;          // warp 0..15
    const int hg = w5 >> 2;         // head in group 0..3
    const int w  = w5 & 3;          // warp within head group
    const int l  = t & 31;
    const int h  = kvh * 4 + hg;
    const int tg = t & 127;         // thread within head group
    const float scale = 0.125f;

    const uint32_t qbase = sb + hg * ATSB;

    // ---- Q staging: each head group stages its own head ----
    {
        const char* Qg = (const char*)(Qh + ((size_t)(b * T_SEQ + qt * 64)) * D_MODEL + h * D_KH);
#pragma unroll
        for (int i = 0; i < 4; i++) {
            int chunk = i * 128 + tg;        // 512 chunks of 16B
            int row = chunk >> 3;
            int cb  = (chunk & 7) << 4;
            CP_ASYNC16(qbase + (uint32_t)(row * 144 + cb), Qg + (size_t)row * (D_MODEL * 2) + cb);
        }
    }
    CP_COMMIT();

    // ---- KV stage helper ----
    const char* KhB = (const char*)(Kh + (size_t)b * T_SEQ * KV_DIM + kvh * D_KH);
    const char* KlB = (const char*)(Kl + (size_t)b * T_SEQ * KV_DIM + kvh * D_KH);
    const char* VhB = (const char*)(Vh + (size_t)b * T_SEQ * KV_DIM + kvh * D_KH);

    auto stage_kv = [&](int kt) {
        int s3 = kt % 3;
        uint32_t dstb = sb + (uint32_t)((4 + 3 * s3) * ATSB);
        size_t src_row0 = (size_t)(kt * 64) * (KV_DIM * 2);
#pragma unroll
        for (int i = 0; i < 3; i++) {
            int chunk = i * 512 + t;         // 1536 chunks = 3 tiles x 512
            int tile = chunk >> 9;
            int idx  = chunk & 511;
            int row  = idx >> 3;
            int cb   = (idx & 7) << 4;
            const char* s = (tile == 0) ? KhB : (tile == 1) ? KlB : VhB;
            CP_ASYNC16(dstb + (uint32_t)(tile * ATSB + row * 144 + cb),
                       s + src_row0 + (size_t)row * (KV_DIM * 2) + cb);
        }
    };

    stage_kv(0);
    CP_COMMIT();
    CP_WAIT1();          // Q ready (stage 0 may still be in flight)
    __syncthreads();

    // ---- Q fragments ----
    uint32_t aq[4][4];
#pragma unroll
    for (int kc = 0; kc < 4; kc++) {
        uint32_t a = qbase + (uint32_t)((w * 16 + (l & 15)) * 144 + kc * 32 + (l >> 4) * 16);
        ldsm_x4(aq[kc][0], aq[kc][1], aq[kc][2], aq[kc][3], a);
    }

    float o[8][4];
#pragma unroll
    for (int i = 0; i < 8; i++)
#pragma unroll
        for (int j = 0; j < 4; j++) o[i][j] = 0.f;
    float m0 = -1e30f, m1 = -1e30f, l0 = 0.f, l1 = 0.f;

    for (int kt = 0; kt <= qt; kt++) {
        if (kt + 1 <= qt) stage_kv(kt + 1);
        CP_COMMIT();     // empty group when nothing staged — keeps wait bookkeeping exact
        CP_WAIT1();      // stage kt complete
        __syncthreads();

        const int s3 = kt % 3;
        const uint32_t kh_ = sb + (uint32_t)((4 + 3 * s3) * ATSB);
        const uint32_t kl_ = kh_ + ATSB;
        const uint32_t vh_ = kh_ + 2 * ATSB;

        // ---- S = Q K^T (Qh·Kh + Qh·Kl) ----
        float s[8][4];
#pragma unroll
        for (int i = 0; i < 8; i++)
#pragma unroll
            for (int j = 0; j < 4; j++) s[i][j] = 0.f;

#pragma unroll
        for (int nt = 0; nt < 8; nt++) {
#pragma unroll
            for (int kcp = 0; kcp < 2; kcp++) {
                uint32_t a = kh_ + (uint32_t)((nt * 8 + (l & 7)) * 144 + kcp * 64 + (l >> 3) * 16);
                uint32_t h0, h1, h2, h3, g0, g1, g2, g3;
                ldsm_x4(h0, h1, h2, h3, a);
                ldsm_x4(g0, g1, g2, g3, a + ATSB);
                uint32_t bh0[2] = {h0, h1}, bh1[2] = {h2, h3};
                uint32_t bl0[2] = {g0, g1}, bl1[2] = {g2, g3};
                mma_f16(s[nt], aq[2 * kcp],     bh0);
                mma_f16(s[nt], aq[2 * kcp],     bl0);
                mma_f16(s[nt], aq[2 * kcp + 1], bh1);
                mma_f16(s[nt], aq[2 * kcp + 1], bl1);
            }
        }

        // ---- scale + causal mask ----
        const int rl0 = w * 16 + (l >> 2);
        const bool diag = (kt == qt);
#pragma unroll
        for (int nt = 0; nt < 8; nt++) {
            int c0 = nt * 8 + (l & 3) * 2;
#pragma unroll
            for (int j = 0; j < 4; j++) {
                float v = s[nt][j] * scale;
                int c = c0 + (j & 1);
                int r = rl0 + ((j >> 1) << 3);
                if (diag && c > r) v = -1e30f;
                s[nt][j] = v;
            }
        }

        // ---- register online softmax ----
        float mx0 = -1e30f, mx1 = -1e30f;
#pragma unroll
        for (int nt = 0; nt < 8; nt++) {
            mx0 = fmaxf(mx0, fmaxf(s[nt][0], s[nt][1]));
            mx1 = fmaxf(mx1, fmaxf(s[nt][2], s[nt][3]));
        }
        mx0 = fmaxf(mx0, __shfl_xor_sync(0xffffffff, mx0, 1));
        mx0 = fmaxf(mx0, __shfl_xor_sync(0xffffffff, mx0, 2));
        mx1 = fmaxf(mx1, __shfl_xor_sync(0xffffffff, mx1, 1));
        mx1 = fmaxf(mx1, __shfl_xor_sync(0xffffffff, mx1, 2));

        float mn0 = fmaxf(m0, mx0), mn1 = fmaxf(m1, mx1);
        float al0 = __expf(m0 - mn0), al1 = __expf(m1 - mn1);
        m0 = mn0; m1 = mn1;

        float sum0 = 0.f, sum1 = 0.f;
#pragma unroll
        for (int nt = 0; nt < 8; nt++) {
            s[nt][0] = __expf(s[nt][0] - mn0); sum0 += s[nt][0];
            s[nt][1] = __expf(s[nt][1] - mn0); sum0 += s[nt][1];
            s[nt][2] = __expf(s[nt][2] - mn1); sum1 += s[nt][2];
            s[nt][3] = __expf(s[nt][3] - mn1); sum1 += s[nt][3];
        }
        sum0 += __shfl_xor_sync(0xffffffff, sum0, 1);
        sum0 += __shfl_xor_sync(0xffffffff, sum0, 2);
        sum1 += __shfl_xor_sync(0xffffffff, sum1, 1);
        sum1 += __shfl_xor_sync(0xffffffff, sum1, 2);
        l0 = l0 * al0 + sum0;
        l1 = l1 * al1 + sum1;

#pragma unroll
        for (int nt = 0; nt < 8; nt++) {
            o[nt][0] *= al0; o[nt][1] *= al0;
            o[nt][2] *= al1; o[nt][3] *= al1;
        }

        // ---- O += P V  (P hi-only fp16) ----
#pragma unroll
        for (int kc2 = 0; kc2 < 4; kc2++) {
            uint32_t aph[4] = {
                pack_f16(s[2 * kc2][0],     s[2 * kc2][1]),
                pack_f16(s[2 * kc2][2],     s[2 * kc2][3]),
                pack_f16(s[2 * kc2 + 1][0], s[2 * kc2 + 1][1]),
                pack_f16(s[2 * kc2 + 1][2], s[2 * kc2 + 1][3])};
#pragma unroll
            for (int ntp = 0; ntp < 4; ntp++) {
                uint32_t a = vh_ + (uint32_t)((kc2 * 16 + (l & 15)) * 144 + ntp * 32 + (l >> 4) * 16);
                uint32_t h0, h1, h2, h3;
                ldsm_x4_t(h0, h1, h2, h3, a);
                uint32_t bh0[2] = {h0, h1}, bh1[2] = {h2, h3};
                mma_f16(o[2 * ntp],     aph, bh0);
                mma_f16(o[2 * ntp + 1], aph, bh1);
            }
        }
        __syncthreads();   // all reads of stage kt done before it is overwritten
    }

    // ---- epilogue: fp16 write ----
    const float il0 = 1.0f / l0, il1 = 1.0f / l1;
    const size_t row0 = (size_t)(b * T_SEQ + qt * 64 + w * 16 + (l >> 2));
    __half* Ob = O + row0 * D_MODEL + h * D_KH + (l & 3) * 2;
#pragma unroll
    for (int nt = 0; nt < 8; nt++) {
        *(uint32_t*)(Ob + nt * 8)               = pack_f16(o[nt][0] * il0, o[nt][1] * il0);
        *(uint32_t*)(Ob + nt * 8 + 8 * D_MODEL) = pack_f16(o[nt][2] * il1, o[nt][3] * il1);
    }
}

// ---------------------------------------------------------------------------
// Launch
// ---------------------------------------------------------------------------
extern "C" void kernel_launch(void* const* d_in, const int* in_sizes, int n_in,
                              void* d_out, int out_size)
{
    const float* x  = (const float*)d_in[0];
    const float* Wq = (const float*)d_in[1];
    const float* Wk = (const float*)d_in[2];
    const float* Wv = (const float*)d_in[3];
    const float* Wo = (const float*)d_in[4];
    float* out = (float*)d_out;

    __half *xh, *qh, *kh, *kl, *vh, *aoh;
    __half *wqh, *wql, *wkh, *wkl, *wvh, *wvl, *woh, *wol;
    cudaGetSymbolAddress((void**)&xh,  g_xh);
    cudaGetSymbolAddress((void**)&qh,  g_qh);
    cudaGetSymbolAddress((void**)&kh,  g_kh);
    cudaGetSymbolAddress((void**)&kl,  g_kl);
    cudaGetSymbolAddress((void**)&vh,  g_vh);
    cudaGetSymbolAddress((void**)&aoh, g_aoh);
    cudaGetSymbolAddress((void**)&wqh, g_wqh); cudaGetSymbolAddress((void**)&wql, g_wql);
    cudaGetSymbolAddress((void**)&wkh, g_wkh); cudaGetSymbolAddress((void**)&wkl, g_wkl);
    cudaGetSymbolAddress((void**)&wvh, g_wvh); cudaGetSymbolAddress((void**)&wvl, g_wvl);
    cudaGetSymbolAddress((void**)&woh, g_woh); cudaGetSymbolAddress((void**)&wol, g_wol);

    cudaFuncSetAttribute(gemm_qkv, cudaFuncAttributeMaxDynamicSharedMemorySize, GEMM_SMEM);
    cudaFuncSetAttribute(gemm_out, cudaFuncAttributeMaxDynamicSharedMemorySize, GEMM_SMEM);
    cudaFuncSetAttribute(attn_hmma, cudaFuncAttributeMaxDynamicSharedMemorySize, ATTN_SMEM);

    const int NX = M_ROWS * D_MODEL;

    to_f16<<<NX / 1024, 256>>>(x, xh, NX);
    split_weights<<<(2 * NWQ + 2 * NWK) / 1024, 256>>>(Wq, Wk, Wv, Wo,
        wqh, wql, wkh, wkl, wvh, wvl, woh, wol);

    gemm_qkv<<<dim3(24, M_ROWS / 128), 256, GEMM_SMEM>>>(
        xh, wqh, wql, wkh, wkl, wvh, wvl, qh, kh, kl, vh);

    attn_hmma<<<dim3(T_SEQ / 64, N_KV, BATCH), 512, ATTN_SMEM>>>(qh, kh, kl, vh, aoh);

    gemm_out<<<dim3(D_MODEL / 128, M_ROWS / 128), 256, GEMM_SMEM>>>(aoh, woh, wol, out);
}

// round 13
// speedup vs baseline: 4.2235x; 1.0225x over previous
#include <cuda_runtime.h>
#include <cuda_fp16.h>
#include <math.h>
#include <cstdint>

#define D_MODEL 2048
#define T_SEQ   2048
#define BATCH   2
#define N_HEADS 32
#define N_KV    8
#define D_KH    64
#define KV_DIM  (N_KV * D_KH)      // 512
#define M_ROWS  (BATCH * T_SEQ)    // 4096
#define GK      2048
#define NWQ     (D_MODEL * D_MODEL)
#define NWK     (KV_DIM * D_MODEL)

// ---------------------------------------------------------------------------
// Scratch (__device__ globals; allocation-free rule)
// ---------------------------------------------------------------------------
__device__ __half g_xh [M_ROWS * D_MODEL];
__device__ __half g_qh [M_ROWS * D_MODEL];
__device__ __half g_kh [M_ROWS * KV_DIM];
__device__ __half g_kl [M_ROWS * KV_DIM];
__device__ __half g_vh [M_ROWS * KV_DIM];
__device__ __half g_aoh[M_ROWS * D_MODEL];

__device__ __half g_wqh[NWQ], g_wql[NWQ];
__device__ __half g_wkh[NWK], g_wkl[NWK];
__device__ __half g_wvh[NWK], g_wvl[NWK];
__device__ __half g_woh[NWQ], g_wol[NWQ];

// ---------------------------------------------------------------------------
// Helpers
// ---------------------------------------------------------------------------
__device__ __forceinline__ uint32_t smem_u32(const void* p) {
    uint32_t a;
    asm("{ .reg .u64 t; cvta.to.shared.u64 t, %1; cvt.u32.u64 %0, t; }" : "=r"(a) : "l"(p));
    return a;
}
#define CP_ASYNC16(dst, src) \
    asm volatile("cp.async.cg.shared.global [%0], [%1], 16;" :: "r"(dst), "l"(src) : "memory")
#define CP_COMMIT() asm volatile("cp.async.commit_group;" ::: "memory")
#define CP_WAIT1()  asm volatile("cp.async.wait_group 1;" ::: "memory")

__device__ __forceinline__ void ldsm_x4(uint32_t& r0, uint32_t& r1, uint32_t& r2, uint32_t& r3, uint32_t a) {
    asm volatile("ldmatrix.sync.aligned.m8n8.x4.shared.b16 {%0,%1,%2,%3}, [%4];"
                 : "=r"(r0), "=r"(r1), "=r"(r2), "=r"(r3) : "r"(a));
}
__device__ __forceinline__ void ldsm_x4_t(uint32_t& r0, uint32_t& r1, uint32_t& r2, uint32_t& r3, uint32_t a) {
    asm volatile("ldmatrix.sync.aligned.m8n8.x4.trans.shared.b16 {%0,%1,%2,%3}, [%4];"
                 : "=r"(r0), "=r"(r1), "=r"(r2), "=r"(r3) : "r"(a));
}
__device__ __forceinline__ void ldsm_x2(uint32_t& r0, uint32_t& r1, uint32_t a) {
    asm volatile("ldmatrix.sync.aligned.m8n8.x2.shared.b16 {%0,%1}, [%2];"
                 : "=r"(r0), "=r"(r1) : "r"(a));
}
__device__ __forceinline__ void mma_f16(float* c, const uint32_t* a, const uint32_t* b) {
    asm volatile("mma.sync.aligned.m16n8k16.row.col.f32.f16.f16.f32 "
                 "{%0,%1,%2,%3}, {%4,%5,%6,%7}, {%8,%9}, {%0,%1,%2,%3};"
                 : "+f"(c[0]), "+f"(c[1]), "+f"(c[2]), "+f"(c[3])
                 : "r"(a[0]), "r"(a[1]), "r"(a[2]), "r"(a[3]), "r"(b[0]), "r"(b[1]));
}
__device__ __forceinline__ uint32_t pack_f16(float lo, float hi) {
    uint32_t r;
    asm("cvt.rn.f16x2.f32 %0, %1, %2;" : "=r"(r) : "f"(hi), "f"(lo));
    return r;
}
__device__ __forceinline__ float f16_round(float v) {
    return __half2float(__float2half_rn(v));
}

// ---------------------------------------------------------------------------
// Conversions
// ---------------------------------------------------------------------------
__global__ __launch_bounds__(256) void to_f16(
    const float* __restrict__ s, __half* __restrict__ d, int n)
{
    int i = (blockIdx.x * 256 + threadIdx.x) * 4;
    if (i >= n) return;
    float4 v = *(const float4*)(s + i);
    *(uint2*)(d + i) = make_uint2(pack_f16(v.x, v.y), pack_f16(v.z, v.w));
}

__global__ __launch_bounds__(256) void split_weights(
    const float* __restrict__ wq, const float* __restrict__ wk,
    const float* __restrict__ wv, const float* __restrict__ wo,
    __half* __restrict__ qh, __half* __restrict__ ql,
    __half* __restrict__ kh, __half* __restrict__ kl,
    __half* __restrict__ vh, __half* __restrict__ vl,
    __half* __restrict__ oh, __half* __restrict__ ol)
{
    int e = (blockIdx.x * 256 + threadIdx.x) * 4;
    const float* s; __half *hi, *lo;
    if (e < NWQ)                 { s = wq; hi = qh; lo = ql; }
    else if (e < NWQ + NWK)      { s = wk; hi = kh; lo = kl; e -= NWQ; }
    else if (e < NWQ + 2 * NWK)  { s = wv; hi = vh; lo = vl; e -= NWQ + NWK; }
    else                         { s = wo; hi = oh; lo = ol; e -= NWQ + 2 * NWK; }
    float4 v = *(const float4*)(s + e);
    float h0 = f16_round(v.x), h1 = f16_round(v.y), h2 = f16_round(v.z), h3 = f16_round(v.w);
    *(uint2*)(hi + e) = make_uint2(pack_f16(h0, h1), pack_f16(h2, h3));
    *(uint2*)(lo + e) = make_uint2(pack_f16(v.x - h0, v.y - h1), pack_f16(v.z - h2, v.w - h3));
}

// ---------------------------------------------------------------------------
// Merged QKV GEMM (unchanged from R11)
// ---------------------------------------------------------------------------
#define RS      80
#define TILE_B  (128 * RS)
#define STG_B   (3 * TILE_B)
#define GEMM_SMEM (2 * STG_B)

__global__ __launch_bounds__(256) void gemm_qkv(
    const __half* __restrict__ Ah,
    const __half* __restrict__ Wqh, const __half* __restrict__ Wql,
    const __half* __restrict__ Wkh, const __half* __restrict__ Wkl,
    const __half* __restrict__ Wvh, const __half* __restrict__ Wvl,
    __half* __restrict__ Qo, __half* __restrict__ Kho, __half* __restrict__ Klo,
    __half* __restrict__ Vo)
{
    extern __shared__ __align__(128) char smem[];
    const uint32_t sb = smem_u32(smem);

    const int t   = threadIdx.x;
    const int wid = t >> 5, l = t & 31;
    const int wm  = wid & 1, wn = wid >> 1;
    const int bx  = blockIdx.x;
    const int bm  = blockIdx.y * 128;

    const __half *Bh, *Bl;
    int mode, bcol;
    if (bx < 16)      { mode = 0; bcol = bx * 128;        Bh = Wqh; Bl = Wql; }
    else if (bx < 20) { mode = 1; bcol = (bx - 16) * 128; Bh = Wkh; Bl = Wkl; }
    else              { mode = 2; bcol = (bx - 20) * 128; Bh = Wvh; Bl = Wvl; }

    const __half* srcs[3] = {Ah + (size_t)bm * GK, Bh + (size_t)bcol * GK, Bl + (size_t)bcol * GK};

    int c_tile[6], c_dst[6];
    size_t c_src[6];
#pragma unroll
    for (int c = 0; c < 6; c++) {
        int chunk = t + c * 256;
        int tile = chunk >> 9;
        int idx  = chunk & 511;
        int row  = idx >> 2;
        int k16  = idx & 3;
        c_tile[c] = tile;
        c_dst[c]  = tile * TILE_B + row * RS + k16 * 16;
        c_src[c]  = (size_t)row * GK + k16 * 8;
    }

    auto load_stage = [&](int s, int k0) {
        uint32_t base = sb + s * STG_B;
#pragma unroll
        for (int c = 0; c < 6; c++)
            CP_ASYNC16(base + c_dst[c], (const char*)(srcs[c_tile[c]] + k0 + c_src[c]));
    };

    float acc[4][4][4];
#pragma unroll
    for (int i = 0; i < 4; i++)
#pragma unroll
        for (int j = 0; j < 4; j++)
#pragma unroll
            for (int k = 0; k < 4; k++) acc[i][j][k] = 0.f;

    const uint32_t aBase = sb + (uint32_t)((wm * 64 + (l & 15)) * RS + (l >> 4) * 16);
    const uint32_t bBase = sb + TILE_B + (uint32_t)((wn * 32 + (l & 7)) * RS + ((l & 15) >> 3) * 16);

    const int nIter = GK / 32;
    load_stage(0, 0);
    CP_COMMIT();

    for (int it = 0; it < nIter; it++) {
        if (it + 1 < nIter) load_stage((it + 1) & 1, (it + 1) * 32);
        CP_COMMIT();
        CP_WAIT1();
        __syncthreads();

        const uint32_t so = (uint32_t)((it & 1) * STG_B);
#pragma unroll
        for (int ks = 0; ks < 2; ks++) {
            const uint32_t kb = so + ks * 32;
            uint32_t ah[4][4], bh[4][2], bl[4][2];
#pragma unroll
            for (int mt = 0; mt < 4; mt++) {
                uint32_t a = aBase + kb + mt * 16 * RS;
                ldsm_x4(ah[mt][0], ah[mt][1], ah[mt][2], ah[mt][3], a);
            }
#pragma unroll
            for (int nt = 0; nt < 4; nt++) {
                uint32_t a = bBase + kb + nt * 8 * RS;
                ldsm_x2(bh[nt][0], bh[nt][1], a);
                ldsm_x2(bl[nt][0], bl[nt][1], a + TILE_B);
            }
#pragma unroll
            for (int mt = 0; mt < 4; mt++)
#pragma unroll
                for (int nt = 0; nt < 4; nt++) {
                    mma_f16(acc[mt][nt], ah[mt], bh[nt]);
                    mma_f16(acc[mt][nt], ah[mt], bl[nt]);
                }
        }
        __syncthreads();
    }

    const int r0c = bm + wm * 64 + (l >> 2);
    const int colr = bcol + wn * 32 + (l & 3) * 2;
    const int stride = (mode == 0) ? D_MODEL : KV_DIM;
#pragma unroll
    for (int mt = 0; mt < 4; mt++) {
#pragma unroll
        for (int nt = 0; nt < 4; nt++) {
            size_t o0 = (size_t)(r0c + mt * 16) * stride + colr + nt * 8;
            size_t o1 = o0 + 8 * stride;
            float a0 = acc[mt][nt][0], a1 = acc[mt][nt][1];
            float a2 = acc[mt][nt][2], a3 = acc[mt][nt][3];
            if (mode == 0) {
                *(uint32_t*)(Qo + o0) = pack_f16(a0, a1);
                *(uint32_t*)(Qo + o1) = pack_f16(a2, a3);
            } else if (mode == 2) {
                *(uint32_t*)(Vo + o0) = pack_f16(a0, a1);
                *(uint32_t*)(Vo + o1) = pack_f16(a2, a3);
            } else {
                float h0 = f16_round(a0), h1 = f16_round(a1);
                float h2 = f16_round(a2), h3 = f16_round(a3);
                *(uint32_t*)(Kho + o0) = pack_f16(h0, h1);
                *(uint32_t*)(Kho + o1) = pack_f16(h2, h3);
                *(uint32_t*)(Klo + o0) = pack_f16(a0 - h0, a1 - h1);
                *(uint32_t*)(Klo + o1) = pack_f16(a2 - h2, a3 - h3);
            }
        }
    }
}

// ---------------------------------------------------------------------------
// Wo GEMM (unchanged from R11)
// ---------------------------------------------------------------------------
__global__ __launch_bounds__(256) void gemm_out(
    const __half* __restrict__ Ah, const __half* __restrict__ Bh,
    const __half* __restrict__ Bl, float* __restrict__ Y)
{
    extern __shared__ __align__(128) char smem[];
    const uint32_t sb = smem_u32(smem);

    const int t   = threadIdx.x;
    const int wid = t >> 5, l = t & 31;
    const int wm  = wid & 1, wn = wid >> 1;
    const int bm  = blockIdx.y * 128, bn = blockIdx.x * 128;

    const __half* srcs[3] = {Ah + (size_t)bm * GK, Bh + (size_t)bn * GK, Bl + (size_t)bn * GK};

    int c_tile[6], c_dst[6];
    size_t c_src[6];
#pragma unroll
    for (int c = 0; c < 6; c++) {
        int chunk = t + c * 256;
        int tile = chunk >> 9;
        int idx  = chunk & 511;
        int row  = idx >> 2;
        int k16  = idx & 3;
        c_tile[c] = tile;
        c_dst[c]  = tile * TILE_B + row * RS + k16 * 16;
        c_src[c]  = (size_t)row * GK + k16 * 8;
    }

    auto load_stage = [&](int s, int k0) {
        uint32_t base = sb + s * STG_B;
#pragma unroll
        for (int c = 0; c < 6; c++)
            CP_ASYNC16(base + c_dst[c], (const char*)(srcs[c_tile[c]] + k0 + c_src[c]));
    };

    float acc[4][4][4];
#pragma unroll
    for (int i = 0; i < 4; i++)
#pragma unroll
        for (int j = 0; j < 4; j++)
#pragma unroll
            for (int k = 0; k < 4; k++) acc[i][j][k] = 0.f;

    const uint32_t aBase = sb + (uint32_t)((wm * 64 + (l & 15)) * RS + (l >> 4) * 16);
    const uint32_t bBase = sb + TILE_B + (uint32_t)((wn * 32 + (l & 7)) * RS + ((l & 15) >> 3) * 16);

    const int nIter = GK / 32;
    load_stage(0, 0);
    CP_COMMIT();

    for (int it = 0; it < nIter; it++) {
        if (it + 1 < nIter) load_stage((it + 1) & 1, (it + 1) * 32);
        CP_COMMIT();
        CP_WAIT1();
        __syncthreads();

        const uint32_t so = (uint32_t)((it & 1) * STG_B);
#pragma unroll
        for (int ks = 0; ks < 2; ks++) {
            const uint32_t kb = so + ks * 32;
            uint32_t ah[4][4], bh[4][2], bl[4][2];
#pragma unroll
            for (int mt = 0; mt < 4; mt++) {
                uint32_t a = aBase + kb + mt * 16 * RS;
                ldsm_x4(ah[mt][0], ah[mt][1], ah[mt][2], ah[mt][3], a);
            }
#pragma unroll
            for (int nt = 0; nt < 4; nt++) {
                uint32_t a = bBase + kb + nt * 8 * RS;
                ldsm_x2(bh[nt][0], bh[nt][1], a);
                ldsm_x2(bl[nt][0], bl[nt][1], a + TILE_B);
            }
#pragma unroll
            for (int mt = 0; mt < 4; mt++)
#pragma unroll
                for (int nt = 0; nt < 4; nt++) {
                    mma_f16(acc[mt][nt], ah[mt], bh[nt]);
                    mma_f16(acc[mt][nt], ah[mt], bl[nt]);
                }
        }
        __syncthreads();
    }

    const int r0c = bm + wm * 64 + (l >> 2);
    const int col0 = bn + wn * 32 + (l & 3) * 2;
#pragma unroll
    for (int mt = 0; mt < 4; mt++) {
#pragma unroll
        for (int nt = 0; nt < 4; nt++) {
            float* y0 = Y + (size_t)(r0c + mt * 16) * D_MODEL + col0 + nt * 8;
            float* y1 = y0 + 8 * D_MODEL;
            y0[0] = acc[mt][nt][0]; y0[1] = acc[mt][nt][1];
            y1[0] = acc[mt][nt][2]; y1[1] = acc[mt][nt][3];
        }
    }
}

// ---------------------------------------------------------------------------
// Flash attention. Changes vs R11:
//  - largest-qt-first CTA order (qt = NT-1 - blockIdx.x)
//  - diagonal tile split out of main loop (mask ALU once per CTA)
//  - exp2-based softmax (scale*log2e folded into score scaling)
// ---------------------------------------------------------------------------
#define ATS  72
#define ATSB (64 * ATS * 2)
#define ATTN_SMEM (13 * ATSB)
#define SCL2 0.1803368801111244f   /* 0.125 * log2(e) */

__global__ __launch_bounds__(512, 1) void attn_hmma(
    const __half* __restrict__ Qh, const __half* __restrict__ Kh,
    const __half* __restrict__ Kl, const __half* __restrict__ Vh,
    __half* __restrict__ O)
{
    extern __shared__ __align__(128) char smem[];
    const uint32_t sb = smem_u32(smem);

    const int qt  = (T_SEQ / 64 - 1) - blockIdx.x;   // big tiles first
    const int kvh = blockIdx.y;
    const int b   = blockIdx.z;

    const int t  = threadIdx.x;
    const int w5 = t >> 5;
    const int hg = w5 >> 2;
    const int w  = w5 & 3;
    const int l  = t & 31;
    const int h  = kvh * 4 + hg;
    const int tg = t & 127;

    const uint32_t qbase = sb + hg * ATSB;

    {
        const char* Qg = (const char*)(Qh + ((size_t)(b * T_SEQ + qt * 64)) * D_MODEL + h * D_KH);
#pragma unroll
        for (int i = 0; i < 4; i++) {
            int chunk = i * 128 + tg;
            int row = chunk >> 3;
            int cb  = (chunk & 7) << 4;
            CP_ASYNC16(qbase + (uint32_t)(row * 144 + cb), Qg + (size_t)row * (D_MODEL * 2) + cb);
        }
    }
    CP_COMMIT();

    const char* KhB = (const char*)(Kh + (size_t)b * T_SEQ * KV_DIM + kvh * D_KH);
    const char* KlB = (const char*)(Kl + (size_t)b * T_SEQ * KV_DIM + kvh * D_KH);
    const char* VhB = (const char*)(Vh + (size_t)b * T_SEQ * KV_DIM + kvh * D_KH);

    auto stage_kv = [&](int kt) {
        int s3 = kt % 3;
        uint32_t dstb = sb + (uint32_t)((4 + 3 * s3) * ATSB);
        size_t src_row0 = (size_t)(kt * 64) * (KV_DIM * 2);
#pragma unroll
        for (int i = 0; i < 3; i++) {
            int chunk = i * 512 + t;
            int tile = chunk >> 9;
            int idx  = chunk & 511;
            int row  = idx >> 3;
            int cb   = (idx & 7) << 4;
            const char* s = (tile == 0) ? KhB : (tile == 1) ? KlB : VhB;
            CP_ASYNC16(dstb + (uint32_t)(tile * ATSB + row * 144 + cb),
                       s + src_row0 + (size_t)row * (KV_DIM * 2) + cb);
        }
    };

    stage_kv(0);
    CP_COMMIT();
    CP_WAIT1();
    __syncthreads();

    uint32_t aq[4][4];
#pragma unroll
    for (int kc = 0; kc < 4; kc++) {
        uint32_t a = qbase + (uint32_t)((w * 16 + (l & 15)) * 144 + kc * 32 + (l >> 4) * 16);
        ldsm_x4(aq[kc][0], aq[kc][1], aq[kc][2], aq[kc][3], a);
    }

    float o[8][4];
#pragma unroll
    for (int i = 0; i < 8; i++)
#pragma unroll
        for (int j = 0; j < 4; j++) o[i][j] = 0.f;
    float m0 = -1e30f, m1 = -1e30f, l0 = 0.f, l1 = 0.f;

    const int rl0 = w * 16 + (l >> 2);

    auto process = [&](int kt, bool domask) {
        const int s3 = kt % 3;
        const uint32_t kh_ = sb + (uint32_t)((4 + 3 * s3) * ATSB);
        const uint32_t vh_ = kh_ + 2 * ATSB;

        float s[8][4];
#pragma unroll
        for (int i = 0; i < 8; i++)
#pragma unroll
            for (int j = 0; j < 4; j++) s[i][j] = 0.f;

#pragma unroll
        for (int nt = 0; nt < 8; nt++) {
#pragma unroll
            for (int kcp = 0; kcp < 2; kcp++) {
                uint32_t a = kh_ + (uint32_t)((nt * 8 + (l & 7)) * 144 + kcp * 64 + (l >> 3) * 16);
                uint32_t h0, h1, h2, h3, g0, g1, g2, g3;
                ldsm_x4(h0, h1, h2, h3, a);
                ldsm_x4(g0, g1, g2, g3, a + ATSB);
                uint32_t bh0[2] = {h0, h1}, bh1[2] = {h2, h3};
                uint32_t bl0[2] = {g0, g1}, bl1[2] = {g2, g3};
                mma_f16(s[nt], aq[2 * kcp],     bh0);
                mma_f16(s[nt], aq[2 * kcp],     bl0);
                mma_f16(s[nt], aq[2 * kcp + 1], bh1);
                mma_f16(s[nt], aq[2 * kcp + 1], bl1);
            }
        }

        if (domask) {
#pragma unroll
            for (int nt = 0; nt < 8; nt++) {
                int c0 = nt * 8 + (l & 3) * 2;
#pragma unroll
                for (int j = 0; j < 4; j++) {
                    int c = c0 + (j & 1);
                    int r = rl0 + ((j >> 1) << 3);
                    float v = s[nt][j] * SCL2;
                    if (c > r) v = -1e30f;
                    s[nt][j] = v;
                }
            }
        } else {
#pragma unroll
            for (int nt = 0; nt < 8; nt++)
#pragma unroll
                for (int j = 0; j < 4; j++) s[nt][j] *= SCL2;
        }

        float mx0 = -1e30f, mx1 = -1e30f;
#pragma unroll
        for (int nt = 0; nt < 8; nt++) {
            mx0 = fmaxf(mx0, fmaxf(s[nt][0], s[nt][1]));
            mx1 = fmaxf(mx1, fmaxf(s[nt][2], s[nt][3]));
        }
        mx0 = fmaxf(mx0, __shfl_xor_sync(0xffffffff, mx0, 1));
        mx0 = fmaxf(mx0, __shfl_xor_sync(0xffffffff, mx0, 2));
        mx1 = fmaxf(mx1, __shfl_xor_sync(0xffffffff, mx1, 1));
        mx1 = fmaxf(mx1, __shfl_xor_sync(0xffffffff, mx1, 2));

        float mn0 = fmaxf(m0, mx0), mn1 = fmaxf(m1, mx1);
        float al0 = exp2f(m0 - mn0), al1 = exp2f(m1 - mn1);
        m0 = mn0; m1 = mn1;

        float sum0 = 0.f, sum1 = 0.f;
#pragma unroll
        for (int nt = 0; nt < 8; nt++) {
            s[nt][0] = exp2f(s[nt][0] - mn0); sum0 += s[nt][0];
            s[nt][1] = exp2f(s[nt][1] - mn0); sum0 += s[nt][1];
            s[nt][2] = exp2f(s[nt][2] - mn1); sum1 += s[nt][2];
            s[nt][3] = exp2f(s[nt][3] - mn1); sum1 += s[nt][3];
        }
        sum0 += __shfl_xor_sync(0xffffffff, sum0, 1);
        sum0 += __shfl_xor_sync(0xffffffff, sum0, 2);
        sum1 += __shfl_xor_sync(0xffffffff, sum1, 1);
        sum1 += __shfl_xor_sync(0xffffffff, sum1, 2);
        l0 = l0 * al0 + sum0;
        l1 = l1 * al1 + sum1;

#pragma unroll
        for (int nt = 0; nt < 8; nt++) {
            o[nt][0] *= al0; o[nt][1] *= al0;
            o[nt][2] *= al1; o[nt][3] *= al1;
        }

#pragma unroll
        for (int kc2 = 0; kc2 < 4; kc2++) {
            uint32_t aph[4] = {
                pack_f16(s[2 * kc2][0],     s[2 * kc2][1]),
                pack_f16(s[2 * kc2][2],     s[2 * kc2][3]),
                pack_f16(s[2 * kc2 + 1][0], s[2 * kc2 + 1][1]),
                pack_f16(s[2 * kc2 + 1][2], s[2 * kc2 + 1][3])};
#pragma unroll
            for (int ntp = 0; ntp < 4; ntp++) {
                uint32_t a = vh_ + (uint32_t)((kc2 * 16 + (l & 15)) * 144 + ntp * 32 + (l >> 4) * 16);
                uint32_t h0, h1, h2, h3;
                ldsm_x4_t(h0, h1, h2, h3, a);
                uint32_t bh0[2] = {h0, h1}, bh1[2] = {h2, h3};
                mma_f16(o[2 * ntp],     aph, bh0);
                mma_f16(o[2 * ntp + 1], aph, bh1);
            }
        }
        __syncthreads();
    };

    // main loop: no mask
    for (int kt = 0; kt < qt; kt++) {
        stage_kv(kt + 1);
        CP_COMMIT();
        CP_WAIT1();
        __syncthreads();
        process(kt, false);
    }
    // diagonal tile
    CP_COMMIT();
    CP_WAIT1();
    __syncthreads();
    process(qt, true);

    const float il0 = 1.0f / l0, il1 = 1.0f / l1;
    const size_t row0 = (size_t)(b * T_SEQ + qt * 64 + w * 16 + (l >> 2));
    __half* Ob = O + row0 * D_MODEL + h * D_KH + (l & 3) * 2;
#pragma unroll
    for (int nt = 0; nt < 8; nt++) {
        *(uint32_t*)(Ob + nt * 8)               = pack_f16(o[nt][0] * il0, o[nt][1] * il0);
        *(uint32_t*)(Ob + nt * 8 + 8 * D_MODEL) = pack_f16(o[nt][2] * il1, o[nt][3] * il1);
    }
}

// ---------------------------------------------------------------------------
// Launch
// ---------------------------------------------------------------------------
extern "C" void kernel_launch(void* const* d_in, const int* in_sizes, int n_in,
                              void* d_out, int out_size)
{
    const float* x  = (const float*)d_in[0];
    const float* Wq = (const float*)d_in[1];
    const float* Wk = (const float*)d_in[2];
    const float* Wv = (const float*)d_in[3];
    const float* Wo = (const float*)d_in[4];
    float* out = (float*)d_out;

    __half *xh, *qh, *kh, *kl, *vh, *aoh;
    __half *wqh, *wql, *wkh, *wkl, *wvh, *wvl, *woh, *wol;
    cudaGetSymbolAddress((void**)&xh,  g_xh);
    cudaGetSymbolAddress((void**)&qh,  g_qh);
    cudaGetSymbolAddress((void**)&kh,  g_kh);
    cudaGetSymbolAddress((void**)&kl,  g_kl);
    cudaGetSymbolAddress((void**)&vh,  g_vh);
    cudaGetSymbolAddress((void**)&aoh, g_aoh);
    cudaGetSymbolAddress((void**)&wqh, g_wqh); cudaGetSymbolAddress((void**)&wql, g_wql);
    cudaGetSymbolAddress((void**)&wkh, g_wkh); cudaGetSymbolAddress((void**)&wkl, g_wkl);
    cudaGetSymbolAddress((void**)&wvh, g_wvh); cudaGetSymbolAddress((void**)&wvl, g_wvl);
    cudaGetSymbolAddress((void**)&woh, g_woh); cudaGetSymbolAddress((void**)&wol, g_wol);

    cudaFuncSetAttribute(gemm_qkv, cudaFuncAttributeMaxDynamicSharedMemorySize, GEMM_SMEM);
    cudaFuncSetAttribute(gemm_out, cudaFuncAttributeMaxDynamicSharedMemorySize, GEMM_SMEM);
    cudaFuncSetAttribute(attn_hmma, cudaFuncAttributeMaxDynamicSharedMemorySize, ATTN_SMEM);

    const int NX = M_ROWS * D_MODEL;

    to_f16<<<NX / 1024, 256>>>(x, xh, NX);
    split_weights<<<(2 * NWQ + 2 * NWK) / 1024, 256>>>(Wq, Wk, Wv, Wo,
        wqh, wql, wkh, wkl, wvh, wvl, woh, wol);

    gemm_qkv<<<dim3(24, M_ROWS / 128), 256, GEMM_SMEM>>>(
        xh, wqh, wql, wkh, wkl, wvh, wvl, qh, kh, kl, vh);

    attn_hmma<<<dim3(T_SEQ / 64, N_KV, BATCH), 512, ATTN_SMEM>>>(qh, kh, kl, vh, aoh);

    gemm_out<<<dim3(D_MODEL / 128, M_ROWS / 128), 256, GEMM_SMEM>>>(aoh, woh, wol, out);
}

// round 16
// speedup vs baseline: 4.3785x; 1.0367x over previous
#include <cuda_runtime.h>
#include <cuda_fp16.h>
#include <math.h>
#include <cstdint>

#define D_MODEL 2048
#define T_SEQ   2048
#define BATCH   2
#define N_HEADS 32
#define N_KV    8
#define D_KH    64
#define KV_DIM  (N_KV * D_KH)      // 512
#define M_ROWS  (BATCH * T_SEQ)    // 4096
#define GK      2048
#define NWQ     (D_MODEL * D_MODEL)
#define NWK     (KV_DIM * D_MODEL)

// ---------------------------------------------------------------------------
// Scratch (__device__ globals; allocation-free rule)
// ---------------------------------------------------------------------------
__device__ __half g_xh [M_ROWS * D_MODEL];
__device__ __half g_qh [M_ROWS * D_MODEL];
__device__ __half g_kh [M_ROWS * KV_DIM];
__device__ __half g_kl [M_ROWS * KV_DIM];
__device__ __half g_vh [M_ROWS * KV_DIM];
__device__ __half g_aoh[M_ROWS * D_MODEL];

__device__ __half g_wqh[NWQ], g_wql[NWQ];
__device__ __half g_wkh[NWK], g_wkl[NWK];
__device__ __half g_wvh[NWK], g_wvl[NWK];
__device__ __half g_woh[NWQ], g_wol[NWQ];

// ---------------------------------------------------------------------------
// Helpers
// ---------------------------------------------------------------------------
__device__ __forceinline__ uint32_t smem_u32(const void* p) {
    uint32_t a;
    asm("{ .reg .u64 t; cvta.to.shared.u64 t, %1; cvt.u32.u64 %0, t; }" : "=r"(a) : "l"(p));
    return a;
}
#define CP_ASYNC16(dst, src) \
    asm volatile("cp.async.cg.shared.global [%0], [%1], 16;" :: "r"(dst), "l"(src) : "memory")
#define CP_COMMIT() asm volatile("cp.async.commit_group;" ::: "memory")
#define CP_WAIT1()  asm volatile("cp.async.wait_group 1;" ::: "memory")

__device__ __forceinline__ void ldsm_x4(uint32_t& r0, uint32_t& r1, uint32_t& r2, uint32_t& r3, uint32_t a) {
    asm volatile("ldmatrix.sync.aligned.m8n8.x4.shared.b16 {%0,%1,%2,%3}, [%4];"
                 : "=r"(r0), "=r"(r1), "=r"(r2), "=r"(r3) : "r"(a));
}
__device__ __forceinline__ void ldsm_x4_t(uint32_t& r0, uint32_t& r1, uint32_t& r2, uint32_t& r3, uint32_t a) {
    asm volatile("ldmatrix.sync.aligned.m8n8.x4.trans.shared.b16 {%0,%1,%2,%3}, [%4];"
                 : "=r"(r0), "=r"(r1), "=r"(r2), "=r"(r3) : "r"(a));
}
__device__ __forceinline__ void ldsm_x2(uint32_t& r0, uint32_t& r1, uint32_t a) {
    asm volatile("ldmatrix.sync.aligned.m8n8.x2.shared.b16 {%0,%1}, [%2];"
                 : "=r"(r0), "=r"(r1) : "r"(a));
}
__device__ __forceinline__ void mma_f16(float* c, const uint32_t* a, const uint32_t* b) {
    asm volatile("mma.sync.aligned.m16n8k16.row.col.f32.f16.f16.f32 "
                 "{%0,%1,%2,%3}, {%4,%5,%6,%7}, {%8,%9}, {%0,%1,%2,%3};"
                 : "+f"(c[0]), "+f"(c[1]), "+f"(c[2]), "+f"(c[3])
                 : "r"(a[0]), "r"(a[1]), "r"(a[2]), "r"(a[3]), "r"(b[0]), "r"(b[1]));
}
__device__ __forceinline__ uint32_t pack_f16(float lo, float hi) {
    uint32_t r;
    asm("cvt.rn.f16x2.f32 %0, %1, %2;" : "=r"(r) : "f"(hi), "f"(lo));
    return r;
}
__device__ __forceinline__ float f16_round(float v) {
    return __half2float(__float2half_rn(v));
}

// ---------------------------------------------------------------------------
// Conversions
// ---------------------------------------------------------------------------
__global__ __launch_bounds__(256) void to_f16(
    const float* __restrict__ s, __half* __restrict__ d, int n)
{
    int i = (blockIdx.x * 256 + threadIdx.x) * 4;
    if (i >= n) return;
    float4 v = *(const float4*)(s + i);
    *(uint2*)(d + i) = make_uint2(pack_f16(v.x, v.y), pack_f16(v.z, v.w));
}

__global__ __launch_bounds__(256) void split_weights(
    const float* __restrict__ wq, const float* __restrict__ wk,
    const float* __restrict__ wv, const float* __restrict__ wo,
    __half* __restrict__ qh, __half* __restrict__ ql,
    __half* __restrict__ kh, __half* __restrict__ kl,
    __half* __restrict__ vh, __half* __restrict__ vl,
    __half* __restrict__ oh, __half* __restrict__ ol)
{
    int e = (blockIdx.x * 256 + threadIdx.x) * 4;
    const float* s; __half *hi, *lo;
    if (e < NWQ)                 { s = wq; hi = qh; lo = ql; }
    else if (e < NWQ + NWK)      { s = wk; hi = kh; lo = kl; e -= NWQ; }
    else if (e < NWQ + 2 * NWK)  { s = wv; hi = vh; lo = vl; e -= NWQ + NWK; }
    else                         { s = wo; hi = oh; lo = ol; e -= NWQ + 2 * NWK; }
    float4 v = *(const float4*)(s + e);
    float h0 = f16_round(v.x), h1 = f16_round(v.y), h2 = f16_round(v.z), h3 = f16_round(v.w);
    *(uint2*)(hi + e) = make_uint2(pack_f16(h0, h1), pack_f16(h2, h3));
    *(uint2*)(lo + e) = make_uint2(pack_f16(v.x - h0, v.y - h1), pack_f16(v.z - h2, v.w - h3));
}

// ---------------------------------------------------------------------------
// Merged QKV GEMM (unchanged)
// ---------------------------------------------------------------------------
#define RS      80
#define TILE_B  (128 * RS)
#define STG_B   (3 * TILE_B)
#define GEMM_SMEM (2 * STG_B)

__global__ __launch_bounds__(256) void gemm_qkv(
    const __half* __restrict__ Ah,
    const __half* __restrict__ Wqh, const __half* __restrict__ Wql,
    const __half* __restrict__ Wkh, const __half* __restrict__ Wkl,
    const __half* __restrict__ Wvh, const __half* __restrict__ Wvl,
    __half* __restrict__ Qo, __half* __restrict__ Kho, __half* __restrict__ Klo,
    __half* __restrict__ Vo)
{
    extern __shared__ __align__(128) char smem[];
    const uint32_t sb = smem_u32(smem);

    const int t   = threadIdx.x;
    const int wid = t >> 5, l = t & 31;
    const int wm  = wid & 1, wn = wid >> 1;
    const int bx  = blockIdx.x;
    const int bm  = blockIdx.y * 128;

    const __half *Bh, *Bl;
    int mode, bcol;
    if (bx < 16)      { mode = 0; bcol = bx * 128;        Bh = Wqh; Bl = Wql; }
    else if (bx < 20) { mode = 1; bcol = (bx - 16) * 128; Bh = Wkh; Bl = Wkl; }
    else              { mode = 2; bcol = (bx - 20) * 128; Bh = Wvh; Bl = Wvl; }

    const __half* srcs[3] = {Ah + (size_t)bm * GK, Bh + (size_t)bcol * GK, Bl + (size_t)bcol * GK};

    int c_tile[6], c_dst[6];
    size_t c_src[6];
#pragma unroll
    for (int c = 0; c < 6; c++) {
        int chunk = t + c * 256;
        int tile = chunk >> 9;
        int idx  = chunk & 511;
        int row  = idx >> 2;
        int k16  = idx & 3;
        c_tile[c] = tile;
        c_dst[c]  = tile * TILE_B + row * RS + k16 * 16;
        c_src[c]  = (size_t)row * GK + k16 * 8;
    }

    auto load_stage = [&](int s, int k0) {
        uint32_t base = sb + s * STG_B;
#pragma unroll
        for (int c = 0; c < 6; c++)
            CP_ASYNC16(base + c_dst[c], (const char*)(srcs[c_tile[c]] + k0 + c_src[c]));
    };

    float acc[4][4][4];
#pragma unroll
    for (int i = 0; i < 4; i++)
#pragma unroll
        for (int j = 0; j < 4; j++)
#pragma unroll
            for (int k = 0; k < 4; k++) acc[i][j][k] = 0.f;

    const uint32_t aBase = sb + (uint32_t)((wm * 64 + (l & 15)) * RS + (l >> 4) * 16);
    const uint32_t bBase = sb + TILE_B + (uint32_t)((wn * 32 + (l & 7)) * RS + ((l & 15) >> 3) * 16);

    const int nIter = GK / 32;
    load_stage(0, 0);
    CP_COMMIT();

    for (int it = 0; it < nIter; it++) {
        if (it + 1 < nIter) load_stage((it + 1) & 1, (it + 1) * 32);
        CP_COMMIT();
        CP_WAIT1();
        __syncthreads();

        const uint32_t so = (uint32_t)((it & 1) * STG_B);
#pragma unroll
        for (int ks = 0; ks < 2; ks++) {
            const uint32_t kb = so + ks * 32;
            uint32_t ah[4][4], bh[4][2], bl[4][2];
#pragma unroll
            for (int mt = 0; mt < 4; mt++) {
                uint32_t a = aBase + kb + mt * 16 * RS;
                ldsm_x4(ah[mt][0], ah[mt][1], ah[mt][2], ah[mt][3], a);
            }
#pragma unroll
            for (int nt = 0; nt < 4; nt++) {
                uint32_t a = bBase + kb + nt * 8 * RS;
                ldsm_x2(bh[nt][0], bh[nt][1], a);
                ldsm_x2(bl[nt][0], bl[nt][1], a + TILE_B);
            }
#pragma unroll
            for (int mt = 0; mt < 4; mt++)
#pragma unroll
                for (int nt = 0; nt < 4; nt++) {
                    mma_f16(acc[mt][nt], ah[mt], bh[nt]);
                    mma_f16(acc[mt][nt], ah[mt], bl[nt]);
                }
        }
        __syncthreads();
    }

    const int r0c = bm + wm * 64 + (l >> 2);
    const int colr = bcol + wn * 32 + (l & 3) * 2;
    const int stride = (mode == 0) ? D_MODEL : KV_DIM;
#pragma unroll
    for (int mt = 0; mt < 4; mt++) {
#pragma unroll
        for (int nt = 0; nt < 4; nt++) {
            size_t o0 = (size_t)(r0c + mt * 16) * stride + colr + nt * 8;
            size_t o1 = o0 + 8 * stride;
            float a0 = acc[mt][nt][0], a1 = acc[mt][nt][1];
            float a2 = acc[mt][nt][2], a3 = acc[mt][nt][3];
            if (mode == 0) {
                *(uint32_t*)(Qo + o0) = pack_f16(a0, a1);
                *(uint32_t*)(Qo + o1) = pack_f16(a2, a3);
            } else if (mode == 2) {
                *(uint32_t*)(Vo + o0) = pack_f16(a0, a1);
                *(uint32_t*)(Vo + o1) = pack_f16(a2, a3);
            } else {
                float h0 = f16_round(a0), h1 = f16_round(a1);
                float h2 = f16_round(a2), h3 = f16_round(a3);
                *(uint32_t*)(Kho + o0) = pack_f16(h0, h1);
                *(uint32_t*)(Kho + o1) = pack_f16(h2, h3);
                *(uint32_t*)(Klo + o0) = pack_f16(a0 - h0, a1 - h1);
                *(uint32_t*)(Klo + o1) = pack_f16(a2 - h2, a3 - h3);
            }
        }
    }
}

// ---------------------------------------------------------------------------
// Wo GEMM (unchanged)
// ---------------------------------------------------------------------------
__global__ __launch_bounds__(256) void gemm_out(
    const __half* __restrict__ Ah, const __half* __restrict__ Bh,
    const __half* __restrict__ Bl, float* __restrict__ Y)
{
    extern __shared__ __align__(128) char smem[];
    const uint32_t sb = smem_u32(smem);

    const int t   = threadIdx.x;
    const int wid = t >> 5, l = t & 31;
    const int wm  = wid & 1, wn = wid >> 1;
    const int bm  = blockIdx.y * 128, bn = blockIdx.x * 128;

    const __half* srcs[3] = {Ah + (size_t)bm * GK, Bh + (size_t)bn * GK, Bl + (size_t)bn * GK};

    int c_tile[6], c_dst[6];
    size_t c_src[6];
#pragma unroll
    for (int c = 0; c < 6; c++) {
        int chunk = t + c * 256;
        int tile = chunk >> 9;
        int idx  = chunk & 511;
        int row  = idx >> 2;
        int k16  = idx & 3;
        c_tile[c] = tile;
        c_dst[c]  = tile * TILE_B + row * RS + k16 * 16;
        c_src[c]  = (size_t)row * GK + k16 * 8;
    }

    auto load_stage = [&](int s, int k0) {
        uint32_t base = sb + s * STG_B;
#pragma unroll
        for (int c = 0; c < 6; c++)
            CP_ASYNC16(base + c_dst[c], (const char*)(srcs[c_tile[c]] + k0 + c_src[c]));
    };

    float acc[4][4][4];
#pragma unroll
    for (int i = 0; i < 4; i++)
#pragma unroll
        for (int j = 0; j < 4; j++)
#pragma unroll
            for (int k = 0; k < 4; k++) acc[i][j][k] = 0.f;

    const uint32_t aBase = sb + (uint32_t)((wm * 64 + (l & 15)) * RS + (l >> 4) * 16);
    const uint32_t bBase = sb + TILE_B + (uint32_t)((wn * 32 + (l & 7)) * RS + ((l & 15) >> 3) * 16);

    const int nIter = GK / 32;
    load_stage(0, 0);
    CP_COMMIT();

    for (int it = 0; it < nIter; it++) {
        if (it + 1 < nIter) load_stage((it + 1) & 1, (it + 1) * 32);
        CP_COMMIT();
        CP_WAIT1();
        __syncthreads();

        const uint32_t so = (uint32_t)((it & 1) * STG_B);
#pragma unroll
        for (int ks = 0; ks < 2; ks++) {
            const uint32_t kb = so + ks * 32;
            uint32_t ah[4][4], bh[4][2], bl[4][2];
#pragma unroll
            for (int mt = 0; mt < 4; mt++) {
                uint32_t a = aBase + kb + mt * 16 * RS;
                ldsm_x4(ah[mt][0], ah[mt][1], ah[mt][2], ah[mt][3], a);
            }
#pragma unroll
            for (int nt = 0; nt < 4; nt++) {
                uint32_t a = bBase + kb + nt * 8 * RS;
                ldsm_x2(bh[nt][0], bh[nt][1], a);
                ldsm_x2(bl[nt][0], bl[nt][1], a + TILE_B);
            }
#pragma unroll
            for (int mt = 0; mt < 4; mt++)
#pragma unroll
                for (int nt = 0; nt < 4; nt++) {
                    mma_f16(acc[mt][nt], ah[mt], bh[nt]);
                    mma_f16(acc[mt][nt], ah[mt], bl[nt]);
                }
        }
        __syncthreads();
    }

    const int r0c = bm + wm * 64 + (l >> 2);
    const int col0 = bn + wn * 32 + (l & 3) * 2;
#pragma unroll
    for (int mt = 0; mt < 4; mt++) {
#pragma unroll
        for (int nt = 0; nt < 4; nt++) {
            float* y0 = Y + (size_t)(r0c + mt * 16) * D_MODEL + col0 + nt * 8;
            float* y1 = y0 + 8 * D_MODEL;
            y0[0] = acc[mt][nt][0]; y0[1] = acc[mt][nt][1];
            y1[0] = acc[mt][nt][2]; y1[1] = acc[mt][nt][3];
        }
    }
}

// ---------------------------------------------------------------------------
// Flash attention. R14: 256-thread CTAs (2 heads), 2 CTAs/SM, single barrier
// per KV tile. Largest-qt-first. exp2 softmax. PV P-hi only.
// ---------------------------------------------------------------------------
#define ATS  72
#define ATSB (64 * ATS * 2)                 // 9216
#define ATTN_SMEM (11 * ATSB)               // 2 Q + 3x(kh,kl,vh) = 101376
#define SCL2 0.1803368801111244f            /* 0.125 * log2(e) */

__global__ __launch_bounds__(256, 2) void attn_hmma(
    const __half* __restrict__ Qh, const __half* __restrict__ Kh,
    const __half* __restrict__ Kl, const __half* __restrict__ Vh,
    __half* __restrict__ O)
{
    extern __shared__ __align__(128) char smem[];
    const uint32_t sb = smem_u32(smem);

    const int qt  = (T_SEQ / 64 - 1) - blockIdx.x;   // big tiles first
    const int kvh = blockIdx.y >> 1;
    const int hp  = blockIdx.y & 1;                  // head pair within kv group
    const int b   = blockIdx.z;

    const int t   = threadIdx.x;
    const int w5  = t >> 5;           // warp 0..7
    const int hgl = w5 >> 2;          // local head 0..1
    const int w   = w5 & 3;           // warp within head
    const int l   = t & 31;
    const int h   = kvh * 4 + hp * 2 + hgl;
    const int tg  = t & 127;

    const uint32_t qbase = sb + hgl * ATSB;

    // ---- Q staging (each 128-thread head group stages its head) ----
    {
        const char* Qg = (const char*)(Qh + ((size_t)(b * T_SEQ + qt * 64)) * D_MODEL + h * D_KH);
#pragma unroll
        for (int i = 0; i < 4; i++) {
            int chunk = i * 128 + tg;
            int row = chunk >> 3;
            int cb  = (chunk & 7) << 4;
            CP_ASYNC16(qbase + (uint32_t)(row * 144 + cb), Qg + (size_t)row * (D_MODEL * 2) + cb);
        }
    }
    CP_COMMIT();

    const char* KhB = (const char*)(Kh + (size_t)b * T_SEQ * KV_DIM + kvh * D_KH);
    const char* KlB = (const char*)(Kl + (size_t)b * T_SEQ * KV_DIM + kvh * D_KH);
    const char* VhB = (const char*)(Vh + (size_t)b * T_SEQ * KV_DIM + kvh * D_KH);

    auto stage_kv = [&](int kt) {
        int s3 = kt % 3;
        uint32_t dstb = sb + (uint32_t)((2 + 3 * s3) * ATSB);
        size_t src_row0 = (size_t)(kt * 64) * (KV_DIM * 2);
#pragma unroll
        for (int i = 0; i < 6; i++) {
            int chunk = i * 256 + t;          // 1536 chunks = 3 tiles x 512
            int tile = chunk >> 9;
            int idx  = chunk & 511;
            int row  = idx >> 3;
            int cb   = (idx & 7) << 4;
            const char* s = (tile == 0) ? KhB : (tile == 1) ? KlB : VhB;
            CP_ASYNC16(dstb + (uint32_t)(tile * ATSB + row * 144 + cb),
                       s + src_row0 + (size_t)row * (KV_DIM * 2) + cb);
        }
    };

    stage_kv(0);
    CP_COMMIT();
    CP_WAIT1();
    __syncthreads();

    uint32_t aq[4][4];
#pragma unroll
    for (int kc = 0; kc < 4; kc++) {
        uint32_t a = qbase + (uint32_t)((w * 16 + (l & 15)) * 144 + kc * 32 + (l >> 4) * 16);
        ldsm_x4(aq[kc][0], aq[kc][1], aq[kc][2], aq[kc][3], a);
    }

    float o[8][4];
#pragma unroll
    for (int i = 0; i < 8; i++)
#pragma unroll
        for (int j = 0; j < 4; j++) o[i][j] = 0.f;
    float m0 = -1e30f, m1 = -1e30f, l0 = 0.f, l1 = 0.f;

    const int rl0 = w * 16 + (l >> 2);

    auto process = [&](int kt, bool domask) {
        const int s3 = kt % 3;
        const uint32_t kh_ = sb + (uint32_t)((2 + 3 * s3) * ATSB);
        const uint32_t vh_ = kh_ + 2 * ATSB;

        float s[8][4];
#pragma unroll
        for (int i = 0; i < 8; i++)
#pragma unroll
            for (int j = 0; j < 4; j++) s[i][j] = 0.f;

#pragma unroll
        for (int nt = 0; nt < 8; nt++) {
#pragma unroll
            for (int kcp = 0; kcp < 2; kcp++) {
                uint32_t a = kh_ + (uint32_t)((nt * 8 + (l & 7)) * 144 + kcp * 64 + (l >> 3) * 16);
                uint32_t h0, h1, h2, h3, g0, g1, g2, g3;
                ldsm_x4(h0, h1, h2, h3, a);
                ldsm_x4(g0, g1, g2, g3, a + ATSB);
                uint32_t bh0[2] = {h0, h1}, bh1[2] = {h2, h3};
                uint32_t bl0[2] = {g0, g1}, bl1[2] = {g2, g3};
                mma_f16(s[nt], aq[2 * kcp],     bh0);
                mma_f16(s[nt], aq[2 * kcp],     bl0);
                mma_f16(s[nt], aq[2 * kcp + 1], bh1);
                mma_f16(s[nt], aq[2 * kcp + 1], bl1);
            }
        }

        if (domask) {
#pragma unroll
            for (int nt = 0; nt < 8; nt++) {
                int c0 = nt * 8 + (l & 3) * 2;
#pragma unroll
                for (int j = 0; j < 4; j++) {
                    int c = c0 + (j & 1);
                    int r = rl0 + ((j >> 1) << 3);
                    float v = s[nt][j] * SCL2;
                    if (c > r) v = -1e30f;
                    s[nt][j] = v;
                }
            }
        } else {
#pragma unroll
            for (int nt = 0; nt < 8; nt++)
#pragma unroll
                for (int j = 0; j < 4; j++) s[nt][j] *= SCL2;
        }

        float mx0 = -1e30f, mx1 = -1e30f;
#pragma unroll
        for (int nt = 0; nt < 8; nt++) {
            mx0 = fmaxf(mx0, fmaxf(s[nt][0], s[nt][1]));
            mx1 = fmaxf(mx1, fmaxf(s[nt][2], s[nt][3]));
        }
        mx0 = fmaxf(mx0, __shfl_xor_sync(0xffffffff, mx0, 1));
        mx0 = fmaxf(mx0, __shfl_xor_sync(0xffffffff, mx0, 2));
        mx1 = fmaxf(mx1, __shfl_xor_sync(0xffffffff, mx1, 1));
        mx1 = fmaxf(mx1, __shfl_xor_sync(0xffffffff, mx1, 2));

        float mn0 = fmaxf(m0, mx0), mn1 = fmaxf(m1, mx1);
        float al0 = exp2f(m0 - mn0), al1 = exp2f(m1 - mn1);
        m0 = mn0; m1 = mn1;

        float sum0 = 0.f, sum1 = 0.f;
#pragma unroll
        for (int nt = 0; nt < 8; nt++) {
            s[nt][0] = exp2f(s[nt][0] - mn0); sum0 += s[nt][0];
            s[nt][1] = exp2f(s[nt][1] - mn0); sum0 += s[nt][1];
            s[nt][2] = exp2f(s[nt][2] - mn1); sum1 += s[nt][2];
            s[nt][3] = exp2f(s[nt][3] - mn1); sum1 += s[nt][3];
        }
        sum0 += __shfl_xor_sync(0xffffffff, sum0, 1);
        sum0 += __shfl_xor_sync(0xffffffff, sum0, 2);
        sum1 += __shfl_xor_sync(0xffffffff, sum1, 1);
        sum1 += __shfl_xor_sync(0xffffffff, sum1, 2);
        l0 = l0 * al0 + sum0;
        l1 = l1 * al1 + sum1;

#pragma unroll
        for (int nt = 0; nt < 8; nt++) {
            o[nt][0] *= al0; o[nt][1] *= al0;
            o[nt][2] *= al1; o[nt][3] *= al1;
        }

#pragma unroll
        for (int kc2 = 0; kc2 < 4; kc2++) {
            uint32_t aph[4] = {
                pack_f16(s[2 * kc2][0],     s[2 * kc2][1]),
                pack_f16(s[2 * kc2][2],     s[2 * kc2][3]),
                pack_f16(s[2 * kc2 + 1][0], s[2 * kc2 + 1][1]),
                pack_f16(s[2 * kc2 + 1][2], s[2 * kc2 + 1][3])};
#pragma unroll
            for (int ntp = 0; ntp < 4; ntp++) {
                uint32_t a = vh_ + (uint32_t)((kc2 * 16 + (l & 15)) * 144 + ntp * 32 + (l >> 4) * 16);
                uint32_t h0, h1, h2, h3;
                ldsm_x4_t(h0, h1, h2, h3, a);
                uint32_t bh0[2] = {h0, h1}, bh1[2] = {h2, h3};
                mma_f16(o[2 * ntp],     aph, bh0);
                mma_f16(o[2 * ntp + 1], aph, bh1);
            }
        }
        // no trailing syncthreads: the pre-process barrier of the NEXT
        // iteration separates this iteration's reads from the overwrite
        // of this stage slot (period-3 ring, writes land 2 barriers later).
    };

    for (int kt = 0; kt < qt; kt++) {
        stage_kv(kt + 1);
        CP_COMMIT();
        CP_WAIT1();
        __syncthreads();
        process(kt, false);
    }
    CP_COMMIT();
    CP_WAIT1();
    __syncthreads();
    process(qt, true);

    const float il0 = 1.0f / l0, il1 = 1.0f / l1;
    const size_t row0 = (size_t)(b * T_SEQ + qt * 64 + w * 16 + (l >> 2));
    __half* Ob = O + row0 * D_MODEL + h * D_KH + (l & 3) * 2;
#pragma unroll
    for (int nt = 0; nt < 8; nt++) {
        *(uint32_t*)(Ob + nt * 8)               = pack_f16(o[nt][0] * il0, o[nt][1] * il0);
        *(uint32_t*)(Ob + nt * 8 + 8 * D_MODEL) = pack_f16(o[nt][2] * il1, o[nt][3] * il1);
    }
}

// ---------------------------------------------------------------------------
// Launch
// ---------------------------------------------------------------------------
extern "C" void kernel_launch(void* const* d_in, const int* in_sizes, int n_in,
                              void* d_out, int out_size)
{
    const float* x  = (const float*)d_in[0];
    const float* Wq = (const float*)d_in[1];
    const float* Wk = (const float*)d_in[2];
    const float* Wv = (const float*)d_in[3];
    const float* Wo = (const float*)d_in[4];
    float* out = (float*)d_out;

    __half *xh, *qh, *kh, *kl, *vh, *aoh;
    __half *wqh, *wql, *wkh, *wkl, *wvh, *wvl, *woh, *wol;
    cudaGetSymbolAddress((void**)&xh,  g_xh);
    cudaGetSymbolAddress((void**)&qh,  g_qh);
    cudaGetSymbolAddress((void**)&kh,  g_kh);
    cudaGetSymbolAddress((void**)&kl,  g_kl);
    cudaGetSymbolAddress((void**)&vh,  g_vh);
    cudaGetSymbolAddress((void**)&aoh, g_aoh);
    cudaGetSymbolAddress((void**)&wqh, g_wqh); cudaGetSymbolAddress((void**)&wql, g_wql);
    cudaGetSymbolAddress((void**)&wkh, g_wkh); cudaGetSymbolAddress((void**)&wkl, g_wkl);
    cudaGetSymbolAddress((void**)&wvh, g_wvh); cudaGetSymbolAddress((void**)&wvl, g_wvl);
    cudaGetSymbolAddress((void**)&woh, g_woh); cudaGetSymbolAddress((void**)&wol, g_wol);

    cudaFuncSetAttribute(gemm_qkv, cudaFuncAttributeMaxDynamicSharedMemorySize, GEMM_SMEM);
    cudaFuncSetAttribute(gemm_out, cudaFuncAttributeMaxDynamicSharedMemorySize, GEMM_SMEM);
    cudaFuncSetAttribute(attn_hmma, cudaFuncAttributeMaxDynamicSharedMemorySize, ATTN_SMEM);

    const int NX = M_ROWS * D_MODEL;

    to_f16<<<NX / 1024, 256>>>(x, xh, NX);
    split_weights<<<(2 * NWQ + 2 * NWK) / 1024, 256>>>(Wq, Wk, Wv, Wo,
        wqh, wql, wkh, wkl, wvh, wvl, woh, wol);

    gemm_qkv<<<dim3(24, M_ROWS / 128), 256, GEMM_SMEM>>>(
        xh, wqh, wql, wkh, wkl, wvh, wvl, qh, kh, kl, vh);

    attn_hmma<<<dim3(T_SEQ / 64, N_KV * 2, BATCH), 256, ATTN_SMEM>>>(qh, kh, kl, vh, aoh);

    gemm_out<<<dim3(D_MODEL / 128, M_ROWS / 128), 256, GEMM_SMEM>>>(aoh, woh, wol, out);
}

// round 17
// speedup vs baseline: 5.1617x; 1.1789x over previous
#include <cuda_runtime.h>
#include <cuda_fp16.h>
#include <math.h>
#include <cstdint>

#define D_MODEL 2048
#define T_SEQ   2048
#define BATCH   2
#define N_HEADS 32
#define N_KV    8
#define D_KH    64
#define KV_DIM  (N_KV * D_KH)      // 512
#define M_ROWS  (BATCH * T_SEQ)    // 4096
#define GK      2048
#define NWQ     (D_MODEL * D_MODEL)
#define NWK     (KV_DIM * D_MODEL)

// ---------------------------------------------------------------------------
// Scratch (__device__ globals; allocation-free rule)
// ---------------------------------------------------------------------------
__device__ __half g_xh [M_ROWS * D_MODEL];
__device__ __half g_qh [M_ROWS * D_MODEL];     // Q fp16
__device__ __half g_kh [M_ROWS * KV_DIM];      // K fp16
__device__ __half g_vh [M_ROWS * KV_DIM];      // V fp16
__device__ __half g_aoh[M_ROWS * D_MODEL];     // attention out fp16

__device__ __half g_wqh[NWQ];                  // Wq hi only
__device__ __half g_wkh[NWK], g_wkl[NWK];      // Wk hi+lo (K accuracy)
__device__ __half g_wvh[NWK];                  // Wv hi only
__device__ __half g_woh[NWQ], g_wol[NWQ];      // Wo hi+lo (final output)

// ---------------------------------------------------------------------------
// Helpers
// ---------------------------------------------------------------------------
__device__ __forceinline__ uint32_t smem_u32(const void* p) {
    uint32_t a;
    asm("{ .reg .u64 t; cvta.to.shared.u64 t, %1; cvt.u32.u64 %0, t; }" : "=r"(a) : "l"(p));
    return a;
}
#define CP_ASYNC16(dst, src) \
    asm volatile("cp.async.cg.shared.global [%0], [%1], 16;" :: "r"(dst), "l"(src) : "memory")
#define CP_COMMIT() asm volatile("cp.async.commit_group;" ::: "memory")
#define CP_WAIT1()  asm volatile("cp.async.wait_group 1;" ::: "memory")

__device__ __forceinline__ void ldsm_x4(uint32_t& r0, uint32_t& r1, uint32_t& r2, uint32_t& r3, uint32_t a) {
    asm volatile("ldmatrix.sync.aligned.m8n8.x4.shared.b16 {%0,%1,%2,%3}, [%4];"
                 : "=r"(r0), "=r"(r1), "=r"(r2), "=r"(r3) : "r"(a));
}
__device__ __forceinline__ void ldsm_x4_t(uint32_t& r0, uint32_t& r1, uint32_t& r2, uint32_t& r3, uint32_t a) {
    asm volatile("ldmatrix.sync.aligned.m8n8.x4.trans.shared.b16 {%0,%1,%2,%3}, [%4];"
                 : "=r"(r0), "=r"(r1), "=r"(r2), "=r"(r3) : "r"(a));
}
__device__ __forceinline__ void ldsm_x2(uint32_t& r0, uint32_t& r1, uint32_t a) {
    asm volatile("ldmatrix.sync.aligned.m8n8.x2.shared.b16 {%0,%1}, [%2];"
                 : "=r"(r0), "=r"(r1) : "r"(a));
}
__device__ __forceinline__ void mma_f16(float* c, const uint32_t* a, const uint32_t* b) {
    asm volatile("mma.sync.aligned.m16n8k16.row.col.f32.f16.f16.f32 "
                 "{%0,%1,%2,%3}, {%4,%5,%6,%7}, {%8,%9}, {%0,%1,%2,%3};"
                 : "+f"(c[0]), "+f"(c[1]), "+f"(c[2]), "+f"(c[3])
                 : "r"(a[0]), "r"(a[1]), "r"(a[2]), "r"(a[3]), "r"(b[0]), "r"(b[1]));
}
__device__ __forceinline__ uint32_t pack_f16(float lo, float hi) {
    uint32_t r;
    asm("cvt.rn.f16x2.f32 %0, %1, %2;" : "=r"(r) : "f"(hi), "f"(lo));
    return r;
}
__device__ __forceinline__ float f16_round(float v) {
    return __half2float(__float2half_rn(v));
}

// ---------------------------------------------------------------------------
// Conversions
// ---------------------------------------------------------------------------
__global__ __launch_bounds__(256) void to_f16(
    const float* __restrict__ s, __half* __restrict__ d, int n)
{
    int i = (blockIdx.x * 256 + threadIdx.x) * 4;
    if (i >= n) return;
    float4 v = *(const float4*)(s + i);
    *(uint2*)(d + i) = make_uint2(pack_f16(v.x, v.y), pack_f16(v.z, v.w));
}

// Weight prep: Wq,Wv -> hi only; Wk,Wo -> hi+lo.
__global__ __launch_bounds__(256) void split_weights(
    const float* __restrict__ wq, const float* __restrict__ wk,
    const float* __restrict__ wv, const float* __restrict__ wo,
    __half* __restrict__ qh,
    __half* __restrict__ kh, __half* __restrict__ kl,
    __half* __restrict__ vh,
    __half* __restrict__ oh, __half* __restrict__ ol)
{
    int e = (blockIdx.x * 256 + threadIdx.x) * 4;
    const float* s; __half *hi, *lo = nullptr;
    if (e < NWQ)                 { s = wq; hi = qh; }
    else if (e < NWQ + NWK)      { s = wk; hi = kh; lo = kl; e -= NWQ; }
    else if (e < NWQ + 2 * NWK)  { s = wv; hi = vh; e -= NWQ + NWK; }
    else                         { s = wo; hi = oh; lo = ol; e -= NWQ + 2 * NWK; }
    float4 v = *(const float4*)(s + e);
    float h0 = f16_round(v.x), h1 = f16_round(v.y), h2 = f16_round(v.z), h3 = f16_round(v.w);
    *(uint2*)(hi + e) = make_uint2(pack_f16(h0, h1), pack_f16(h2, h3));
    if (lo)
        *(uint2*)(lo + e) = make_uint2(pack_f16(v.x - h0, v.y - h1), pack_f16(v.z - h2, v.w - h3));
}

// ---------------------------------------------------------------------------
// Merged QKV GEMM. Q/V regions: 1-term (Bh only). K region: 2-term (Bh+Bl).
// All outputs fp16 hi-only.
// ---------------------------------------------------------------------------
#define RS      80
#define TILE_B  (128 * RS)
#define STG_B   (3 * TILE_B)
#define GEMM_SMEM (2 * STG_B)

__global__ __launch_bounds__(256) void gemm_qkv(
    const __half* __restrict__ Ah,
    const __half* __restrict__ Wqh,
    const __half* __restrict__ Wkh, const __half* __restrict__ Wkl,
    const __half* __restrict__ Wvh,
    __half* __restrict__ Qo, __half* __restrict__ Ko, __half* __restrict__ Vo)
{
    extern __shared__ __align__(128) char smem[];
    const uint32_t sb = smem_u32(smem);

    const int t   = threadIdx.x;
    const int wid = t >> 5, l = t & 31;
    const int wm  = wid & 1, wn = wid >> 1;
    const int bx  = blockIdx.x;
    const int bm  = blockIdx.y * 128;

    const __half *Bh, *Bl = nullptr;
    int mode, bcol;
    if (bx < 16)      { mode = 0; bcol = bx * 128;        Bh = Wqh; }
    else if (bx < 20) { mode = 1; bcol = (bx - 16) * 128; Bh = Wkh; Bl = Wkl; }
    else              { mode = 2; bcol = (bx - 20) * 128; Bh = Wvh; }
    const bool use_lo = (mode == 1);
    const int nch = use_lo ? 6 : 4;      // cp.async chunks per thread

    const __half* srcs[3] = {Ah + (size_t)bm * GK, Bh + (size_t)bcol * GK,
                             use_lo ? (Bl + (size_t)bcol * GK) : (Bh + (size_t)bcol * GK)};

    int c_tile[6], c_dst[6];
    size_t c_src[6];
#pragma unroll
    for (int c = 0; c < 6; c++) {
        int chunk = t + c * 256;
        int tile = chunk >> 9;           // c=0,1 -> A; c=2,3 -> Bh; c=4,5 -> Bl
        int idx  = chunk & 511;
        int row  = idx >> 2;
        int k16  = idx & 3;
        c_tile[c] = tile;
        c_dst[c]  = tile * TILE_B + row * RS + k16 * 16;
        c_src[c]  = (size_t)row * GK + k16 * 8;
    }

    auto load_stage = [&](int s, int k0) {
        uint32_t base = sb + s * STG_B;
        for (int c = 0; c < nch; c++)
            CP_ASYNC16(base + c_dst[c], (const char*)(srcs[c_tile[c]] + k0 + c_src[c]));
    };

    float acc[4][4][4];
#pragma unroll
    for (int i = 0; i < 4; i++)
#pragma unroll
        for (int j = 0; j < 4; j++)
#pragma unroll
            for (int k = 0; k < 4; k++) acc[i][j][k] = 0.f;

    const uint32_t aBase = sb + (uint32_t)((wm * 64 + (l & 15)) * RS + (l >> 4) * 16);
    const uint32_t bBase = sb + TILE_B + (uint32_t)((wn * 32 + (l & 7)) * RS + ((l & 15) >> 3) * 16);

    const int nIter = GK / 32;
    load_stage(0, 0);
    CP_COMMIT();

    for (int it = 0; it < nIter; it++) {
        if (it + 1 < nIter) load_stage((it + 1) & 1, (it + 1) * 32);
        CP_COMMIT();
        CP_WAIT1();
        __syncthreads();

        const uint32_t so = (uint32_t)((it & 1) * STG_B);
#pragma unroll
        for (int ks = 0; ks < 2; ks++) {
            const uint32_t kb = so + ks * 32;
            uint32_t ah[4][4], bh[4][2], bl[4][2];
#pragma unroll
            for (int mt = 0; mt < 4; mt++) {
                uint32_t a = aBase + kb + mt * 16 * RS;
                ldsm_x4(ah[mt][0], ah[mt][1], ah[mt][2], ah[mt][3], a);
            }
#pragma unroll
            for (int nt = 0; nt < 4; nt++) {
                uint32_t a = bBase + kb + nt * 8 * RS;
                ldsm_x2(bh[nt][0], bh[nt][1], a);
            }
            if (use_lo) {
#pragma unroll
                for (int nt = 0; nt < 4; nt++) {
                    uint32_t a = bBase + kb + nt * 8 * RS;
                    ldsm_x2(bl[nt][0], bl[nt][1], a + TILE_B);
                }
            }
#pragma unroll
            for (int mt = 0; mt < 4; mt++)
#pragma unroll
                for (int nt = 0; nt < 4; nt++) {
                    mma_f16(acc[mt][nt], ah[mt], bh[nt]);
                    if (use_lo) mma_f16(acc[mt][nt], ah[mt], bl[nt]);
                }
        }
        __syncthreads();
    }

    // Epilogue: fp16 hi-only writes, region-selected output
    __half* outp = (mode == 0) ? Qo : (mode == 1) ? Ko : Vo;
    const int stride = (mode == 0) ? D_MODEL : KV_DIM;
    const int r0c = bm + wm * 64 + (l >> 2);
    const int colr = bcol + wn * 32 + (l & 3) * 2;
#pragma unroll
    for (int mt = 0; mt < 4; mt++) {
#pragma unroll
        for (int nt = 0; nt < 4; nt++) {
            size_t o0 = (size_t)(r0c + mt * 16) * stride + colr + nt * 8;
            size_t o1 = o0 + 8 * stride;
            *(uint32_t*)(outp + o0) = pack_f16(acc[mt][nt][0], acc[mt][nt][1]);
            *(uint32_t*)(outp + o1) = pack_f16(acc[mt][nt][2], acc[mt][nt][3]);
        }
    }
}

// ---------------------------------------------------------------------------
// Wo GEMM: 2-term, fp32 output (unchanged)
// ---------------------------------------------------------------------------
__global__ __launch_bounds__(256) void gemm_out(
    const __half* __restrict__ Ah, const __half* __restrict__ Bh,
    const __half* __restrict__ Bl, float* __restrict__ Y)
{
    extern __shared__ __align__(128) char smem[];
    const uint32_t sb = smem_u32(smem);

    const int t   = threadIdx.x;
    const int wid = t >> 5, l = t & 31;
    const int wm  = wid & 1, wn = wid >> 1;
    const int bm  = blockIdx.y * 128, bn = blockIdx.x * 128;

    const __half* srcs[3] = {Ah + (size_t)bm * GK, Bh + (size_t)bn * GK, Bl + (size_t)bn * GK};

    int c_tile[6], c_dst[6];
    size_t c_src[6];
#pragma unroll
    for (int c = 0; c < 6; c++) {
        int chunk = t + c * 256;
        int tile = chunk >> 9;
        int idx  = chunk & 511;
        int row  = idx >> 2;
        int k16  = idx & 3;
        c_tile[c] = tile;
        c_dst[c]  = tile * TILE_B + row * RS + k16 * 16;
        c_src[c]  = (size_t)row * GK + k16 * 8;
    }

    auto load_stage = [&](int s, int k0) {
        uint32_t base = sb + s * STG_B;
#pragma unroll
        for (int c = 0; c < 6; c++)
            CP_ASYNC16(base + c_dst[c], (const char*)(srcs[c_tile[c]] + k0 + c_src[c]));
    };

    float acc[4][4][4];
#pragma unroll
    for (int i = 0; i < 4; i++)
#pragma unroll
        for (int j = 0; j < 4; j++)
#pragma unroll
            for (int k = 0; k < 4; k++) acc[i][j][k] = 0.f;

    const uint32_t aBase = sb + (uint32_t)((wm * 64 + (l & 15)) * RS + (l >> 4) * 16);
    const uint32_t bBase = sb + TILE_B + (uint32_t)((wn * 32 + (l & 7)) * RS + ((l & 15) >> 3) * 16);

    const int nIter = GK / 32;
    load_stage(0, 0);
    CP_COMMIT();

    for (int it = 0; it < nIter; it++) {
        if (it + 1 < nIter) load_stage((it + 1) & 1, (it + 1) * 32);
        CP_COMMIT();
        CP_WAIT1();
        __syncthreads();

        const uint32_t so = (uint32_t)((it & 1) * STG_B);
#pragma unroll
        for (int ks = 0; ks < 2; ks++) {
            const uint32_t kb = so + ks * 32;
            uint32_t ah[4][4], bh[4][2], bl[4][2];
#pragma unroll
            for (int mt = 0; mt < 4; mt++) {
                uint32_t a = aBase + kb + mt * 16 * RS;
                ldsm_x4(ah[mt][0], ah[mt][1], ah[mt][2], ah[mt][3], a);
            }
#pragma unroll
            for (int nt = 0; nt < 4; nt++) {
                uint32_t a = bBase + kb + nt * 8 * RS;
                ldsm_x2(bh[nt][0], bh[nt][1], a);
                ldsm_x2(bl[nt][0], bl[nt][1], a + TILE_B);
            }
#pragma unroll
            for (int mt = 0; mt < 4; mt++)
#pragma unroll
                for (int nt = 0; nt < 4; nt++) {
                    mma_f16(acc[mt][nt], ah[mt], bh[nt]);
                    mma_f16(acc[mt][nt], ah[mt], bl[nt]);
                }
        }
        __syncthreads();
    }

    const int r0c = bm + wm * 64 + (l >> 2);
    const int col0 = bn + wn * 32 + (l & 3) * 2;
#pragma unroll
    for (int mt = 0; mt < 4; mt++) {
#pragma unroll
        for (int nt = 0; nt < 4; nt++) {
            float* y0 = Y + (size_t)(r0c + mt * 16) * D_MODEL + col0 + nt * 8;
            float* y1 = y0 + 8 * D_MODEL;
            y0[0] = acc[mt][nt][0]; y0[1] = acc[mt][nt][1];
            y1[0] = acc[mt][nt][2]; y1[1] = acc[mt][nt][3];
        }
    }
}

// ---------------------------------------------------------------------------
// Flash attention. R17: K hi-only (QK 2 MMAs per fragment pair), 2-tile KV
// stages, smem 8 tiles. 256 thr, 2 CTAs/SM, largest-qt-first, exp2 softmax.
// ---------------------------------------------------------------------------
#define ATS  72
#define ATSB (64 * ATS * 2)                 // 9216
#define ATTN_SMEM (8 * ATSB)                // 2 Q + 3x(kh,vh) = 73728
#define SCL2 0.1803368801111244f            /* 0.125 * log2(e) */

__global__ __launch_bounds__(256, 2) void attn_hmma(
    const __half* __restrict__ Qh, const __half* __restrict__ Kh,
    const __half* __restrict__ Vh, __half* __restrict__ O)
{
    extern __shared__ __align__(128) char smem[];
    const uint32_t sb = smem_u32(smem);

    const int qt  = (T_SEQ / 64 - 1) - blockIdx.x;   // big tiles first
    const int kvh = blockIdx.y >> 1;
    const int hp  = blockIdx.y & 1;
    const int b   = blockIdx.z;

    const int t   = threadIdx.x;
    const int w5  = t >> 5;
    const int hgl = w5 >> 2;
    const int w   = w5 & 3;
    const int l   = t & 31;
    const int h   = kvh * 4 + hp * 2 + hgl;
    const int tg  = t & 127;

    const uint32_t qbase = sb + hgl * ATSB;

    // ---- Q staging ----
    {
        const char* Qg = (const char*)(Qh + ((size_t)(b * T_SEQ + qt * 64)) * D_MODEL + h * D_KH);
#pragma unroll
        for (int i = 0; i < 4; i++) {
            int chunk = i * 128 + tg;
            int row = chunk >> 3;
            int cb  = (chunk & 7) << 4;
            CP_ASYNC16(qbase + (uint32_t)(row * 144 + cb), Qg + (size_t)row * (D_MODEL * 2) + cb);
        }
    }
    CP_COMMIT();

    const char* KhB = (const char*)(Kh + (size_t)b * T_SEQ * KV_DIM + kvh * D_KH);
    const char* VhB = (const char*)(Vh + (size_t)b * T_SEQ * KV_DIM + kvh * D_KH);

    auto stage_kv = [&](int kt) {
        int s3 = kt % 3;
        uint32_t dstb = sb + (uint32_t)((2 + 2 * s3) * ATSB);
        size_t src_row0 = (size_t)(kt * 64) * (KV_DIM * 2);
#pragma unroll
        for (int i = 0; i < 4; i++) {
            int chunk = i * 256 + t;          // 1024 chunks = 2 tiles x 512
            int tile = chunk >> 9;
            int idx  = chunk & 511;
            int row  = idx >> 3;
            int cb   = (idx & 7) << 4;
            const char* s = (tile == 0) ? KhB : VhB;
            CP_ASYNC16(dstb + (uint32_t)(tile * ATSB + row * 144 + cb),
                       s + src_row0 + (size_t)row * (KV_DIM * 2) + cb);
        }
    };

    stage_kv(0);
    CP_COMMIT();
    CP_WAIT1();
    __syncthreads();

    uint32_t aq[4][4];
#pragma unroll
    for (int kc = 0; kc < 4; kc++) {
        uint32_t a = qbase + (uint32_t)((w * 16 + (l & 15)) * 144 + kc * 32 + (l >> 4) * 16);
        ldsm_x4(aq[kc][0], aq[kc][1], aq[kc][2], aq[kc][3], a);
    }

    float o[8][4];
#pragma unroll
    for (int i = 0; i < 8; i++)
#pragma unroll
        for (int j = 0; j < 4; j++) o[i][j] = 0.f;
    float m0 = -1e30f, m1 = -1e30f, l0 = 0.f, l1 = 0.f;

    const int rl0 = w * 16 + (l >> 2);

    auto process = [&](int kt, bool domask) {
        const int s3 = kt % 3;
        const uint32_t kh_ = sb + (uint32_t)((2 + 2 * s3) * ATSB);
        const uint32_t vh_ = kh_ + ATSB;

        float s[8][4];
#pragma unroll
        for (int i = 0; i < 8; i++)
#pragma unroll
            for (int j = 0; j < 4; j++) s[i][j] = 0.f;

#pragma unroll
        for (int nt = 0; nt < 8; nt++) {
#pragma unroll
            for (int kcp = 0; kcp < 2; kcp++) {
                uint32_t a = kh_ + (uint32_t)((nt * 8 + (l & 7)) * 144 + kcp * 64 + (l >> 3) * 16);
                uint32_t h0, h1, h2, h3;
                ldsm_x4(h0, h1, h2, h3, a);
                uint32_t bh0[2] = {h0, h1}, bh1[2] = {h2, h3};
                mma_f16(s[nt], aq[2 * kcp],     bh0);
                mma_f16(s[nt], aq[2 * kcp + 1], bh1);
            }
        }

        if (domask) {
#pragma unroll
            for (int nt = 0; nt < 8; nt++) {
                int c0 = nt * 8 + (l & 3) * 2;
#pragma unroll
                for (int j = 0; j < 4; j++) {
                    int c = c0 + (j & 1);
                    int r = rl0 + ((j >> 1) << 3);
                    float v = s[nt][j] * SCL2;
                    if (c > r) v = -1e30f;
                    s[nt][j] = v;
                }
            }
        } else {
#pragma unroll
            for (int nt = 0; nt < 8; nt++)
#pragma unroll
                for (int j = 0; j < 4; j++) s[nt][j] *= SCL2;
        }

        float mx0 = -1e30f, mx1 = -1e30f;
#pragma unroll
        for (int nt = 0; nt < 8; nt++) {
            mx0 = fmaxf(mx0, fmaxf(s[nt][0], s[nt][1]));
            mx1 = fmaxf(mx1, fmaxf(s[nt][2], s[nt][3]));
        }
        mx0 = fmaxf(mx0, __shfl_xor_sync(0xffffffff, mx0, 1));
        mx0 = fmaxf(mx0, __shfl_xor_sync(0xffffffff, mx0, 2));
        mx1 = fmaxf(mx1, __shfl_xor_sync(0xffffffff, mx1, 1));
        mx1 = fmaxf(mx1, __shfl_xor_sync(0xffffffff, mx1, 2));

        float mn0 = fmaxf(m0, mx0), mn1 = fmaxf(m1, mx1);
        float al0 = exp2f(m0 - mn0), al1 = exp2f(m1 - mn1);
        m0 = mn0; m1 = mn1;

        float sum0 = 0.f, sum1 = 0.f;
#pragma unroll
        for (int nt = 0; nt < 8; nt++) {
            s[nt][0] = exp2f(s[nt][0] - mn0); sum0 += s[nt][0];
            s[nt][1] = exp2f(s[nt][1] - mn0); sum0 += s[nt][1];
            s[nt][2] = exp2f(s[nt][2] - mn1); sum1 += s[nt][2];
            s[nt][3] = exp2f(s[nt][3] - mn1); sum1 += s[nt][3];
        }
        sum0 += __shfl_xor_sync(0xffffffff, sum0, 1);
        sum0 += __shfl_xor_sync(0xffffffff, sum0, 2);
        sum1 += __shfl_xor_sync(0xffffffff, sum1, 1);
        sum1 += __shfl_xor_sync(0xffffffff, sum1, 2);
        l0 = l0 * al0 + sum0;
        l1 = l1 * al1 + sum1;

#pragma unroll
        for (int nt = 0; nt < 8; nt++) {
            o[nt][0] *= al0; o[nt][1] *= al0;
            o[nt][2] *= al1; o[nt][3] *= al1;
        }

#pragma unroll
        for (int kc2 = 0; kc2 < 4; kc2++) {
            uint32_t aph[4] = {
                pack_f16(s[2 * kc2][0],     s[2 * kc2][1]),
                pack_f16(s[2 * kc2][2],     s[2 * kc2][3]),
                pack_f16(s[2 * kc2 + 1][0], s[2 * kc2 + 1][1]),
                pack_f16(s[2 * kc2 + 1][2], s[2 * kc2 + 1][3])};
#pragma unroll
            for (int ntp = 0; ntp < 4; ntp++) {
                uint32_t a = vh_ + (uint32_t)((kc2 * 16 + (l & 15)) * 144 + ntp * 32 + (l >> 4) * 16);
                uint32_t h0, h1, h2, h3;
                ldsm_x4_t(h0, h1, h2, h3, a);
                uint32_t bh0[2] = {h0, h1}, bh1[2] = {h2, h3};
                mma_f16(o[2 * ntp],     aph, bh0);
                mma_f16(o[2 * ntp + 1], aph, bh1);
            }
        }
        // no trailing syncthreads: the next iteration's pre-process barrier
        // separates these reads from the slot's overwrite (period-3 ring).
    };

    for (int kt = 0; kt < qt; kt++) {
        stage_kv(kt + 1);
        CP_COMMIT();
        CP_WAIT1();
        __syncthreads();
        process(kt, false);
    }
    CP_COMMIT();
    CP_WAIT1();
    __syncthreads();
    process(qt, true);

    const float il0 = 1.0f / l0, il1 = 1.0f / l1;
    const size_t row0 = (size_t)(b * T_SEQ + qt * 64 + w * 16 + (l >> 2));
    __half* Ob = O + row0 * D_MODEL + h * D_KH + (l & 3) * 2;
#pragma unroll
    for (int nt = 0; nt < 8; nt++) {
        *(uint32_t*)(Ob + nt * 8)               = pack_f16(o[nt][0] * il0, o[nt][1] * il0);
        *(uint32_t*)(Ob + nt * 8 + 8 * D_MODEL) = pack_f16(o[nt][2] * il1, o[nt][3] * il1);
    }
}

// ---------------------------------------------------------------------------
// Launch
// ---------------------------------------------------------------------------
extern "C" void kernel_launch(void* const* d_in, const int* in_sizes, int n_in,
                              void* d_out, int out_size)
{
    const float* x  = (const float*)d_in[0];
    const float* Wq = (const float*)d_in[1];
    const float* Wk = (const float*)d_in[2];
    const float* Wv = (const float*)d_in[3];
    const float* Wo = (const float*)d_in[4];
    float* out = (float*)d_out;

    __half *xh, *qh, *kh, *vh, *aoh;
    __half *wqh, *wkh, *wkl, *wvh, *woh, *wol;
    cudaGetSymbolAddress((void**)&xh,  g_xh);
    cudaGetSymbolAddress((void**)&qh,  g_qh);
    cudaGetSymbolAddress((void**)&kh,  g_kh);
    cudaGetSymbolAddress((void**)&vh,  g_vh);
    cudaGetSymbolAddress((void**)&aoh, g_aoh);
    cudaGetSymbolAddress((void**)&wqh, g_wqh);
    cudaGetSymbolAddress((void**)&wkh, g_wkh); cudaGetSymbolAddress((void**)&wkl, g_wkl);
    cudaGetSymbolAddress((void**)&wvh, g_wvh);
    cudaGetSymbolAddress((void**)&woh, g_woh); cudaGetSymbolAddress((void**)&wol, g_wol);

    cudaFuncSetAttribute(gemm_qkv, cudaFuncAttributeMaxDynamicSharedMemorySize, GEMM_SMEM);
    cudaFuncSetAttribute(gemm_out, cudaFuncAttributeMaxDynamicSharedMemorySize, GEMM_SMEM);
    cudaFuncSetAttribute(attn_hmma, cudaFuncAttributeMaxDynamicSharedMemorySize, ATTN_SMEM);

    const int NX = M_ROWS * D_MODEL;

    to_f16<<<NX / 1024, 256>>>(x, xh, NX);
    split_weights<<<(2 * NWQ + 2 * NWK) / 1024, 256>>>(Wq, Wk, Wv, Wo,
        wqh, wkh, wkl, wvh, woh, wol);

    gemm_qkv<<<dim3(24, M_ROWS / 128), 256, GEMM_SMEM>>>(
        xh, wqh, wkh, wkl, wvh, qh, kh, vh);

    attn_hmma<<<dim3(T_SEQ / 64, N_KV * 2, BATCH), 256, ATTN_SMEM>>>(qh, kh, vh, aoh);

    gemm_out<<<dim3(D_MODEL / 128, M_ROWS / 128), 256, GEMM_SMEM>>>(aoh, woh, wol, out);
}